// round 2
// baseline (speedup 1.0000x reference)
#include <cuda_runtime.h>
#include <cuda_bf16.h>
#include <math.h>

// Problem dims (fixed by the dataset)
#define D      2048
#define TOKENS 8192

#define POW_ITERS 12
#define BJ_ITERS  40

// ---------------- scratch (no allocs allowed) ----------------
__device__ __align__(16) float g_theta[D * D];
__device__ __align__(16) float g_tmpT [D * D];
__device__ __align__(16) float g_A    [D * D];
__device__ __align__(16) float g_u[D];
__device__ __align__(16) float g_v[D];
__device__ __align__(16) float g_part[16 * D];
__device__ float g_sigma;

// ---------------- small vector kernels ----------------

// u[j] = mean over rows of W[:, j]  (coalesced: thread j walks column j)
__global__ void colmean_k(const float* __restrict__ W, float* __restrict__ u) {
    int j = blockIdx.x * blockDim.x + threadIdx.x;
    float s = 0.f;
    for (int i = 0; i < D; ++i) s += W[i * D + j];
    u[j] = s * (1.0f / D);
}

// In-place l2 normalize of a length-D vector; optionally writes the norm.
// Single block -> deterministic tree reduction.
__global__ void normalize_k(float* __restrict__ v, float* __restrict__ out_norm) {
    __shared__ float red[1024];
    int t = threadIdx.x;
    float s = 0.f;
    for (int i = t; i < D; i += 1024) { float x = v[i]; s += x * x; }
    red[t] = s;
    __syncthreads();
    for (int o = 512; o > 0; o >>= 1) {
        if (t < o) red[t] += red[t + o];
        __syncthreads();
    }
    if (t == 0) {
        float nrm = sqrtf(red[0]);
        if (out_norm) *out_norm = nrm;
        red[0] = 1.0f / (nrm + 1e-10f);
    }
    __syncthreads();
    float iv = red[0];
    for (int i = t; i < D; i += 1024) v[i] *= iv;
}

// y = W @ u   (one warp per row)
__global__ void matvec_row_k(const float* __restrict__ W, const float* __restrict__ u,
                             float* __restrict__ y) {
    int warp = threadIdx.x >> 5, lane = threadIdx.x & 31;
    int row = blockIdx.x * 8 + warp;
    const float* wr = W + (size_t)row * D;
    float s = 0.f;
    for (int c = lane; c < D; c += 32) s += wr[c] * u[c];
    #pragma unroll
    for (int o = 16; o > 0; o >>= 1) s += __shfl_xor_sync(0xffffffffu, s, o);
    if (lane == 0) y[row] = s;
}

// partial z over a row-chunk:  part[by][j] = sum_{i in chunk} v[i] * W[i][j]
__global__ void matvec_col_part_k(const float* __restrict__ W, const float* __restrict__ v,
                                  float* __restrict__ part) {
    int j = blockIdx.x * 256 + threadIdx.x;
    int r0 = blockIdx.y * 128;
    float s = 0.f;
    #pragma unroll 4
    for (int i = 0; i < 128; ++i) s += v[r0 + i] * W[(size_t)(r0 + i) * D + j];
    part[blockIdx.y * D + j] = s;
}

// z[j] = sum over 16 chunks of part[c][j]
__global__ void part_reduce_k(const float* __restrict__ part, float* __restrict__ z) {
    int j = blockIdx.x * 256 + threadIdx.x;
    float s = 0.f;
    #pragma unroll
    for (int c = 0; c < 16; ++c) s += part[c * D + j];
    z[j] = s;
}

// theta = W / (sigma + 1e-5)
__global__ void scale_k(const float* __restrict__ W, float* __restrict__ T,
                        const float* __restrict__ sig) {
    float inv = 1.0f / (*sig + 1e-5f);
    int i = blockIdx.x * blockDim.x + threadIdx.x;   // one float4 per thread
    float4 w = reinterpret_cast<const float4*>(W)[i];
    w.x *= inv; w.y *= inv; w.z *= inv; w.w *= inv;
    reinterpret_cast<float4*>(T)[i] = w;
}

// ---------------- SGEMM: 128x128x16 tiles, 8x8 per thread ----------------
// EPI 0:  C = A(^T) B
// EPI 1:  C = 1.5*E - 0.5*(A B)         (E is D x D, same indexing as C)
// EPI 2:  C = (A B) + E[col]            (bias)
#define BM 128
#define BN 128
#define BK 16

template<bool TRANSA, int EPI>
__global__ void __launch_bounds__(256, 2)
sgemm_k(const float* __restrict__ A, const float* __restrict__ B,
        float* __restrict__ C, const float* __restrict__ E) {
    __shared__ float As[BK][BM + 4];
    __shared__ float Bs[BK][BN + 4];

    int tid = threadIdx.x;
    int tx = tid & 15, ty = tid >> 4;
    int row0 = blockIdx.y * BM;
    int col0 = blockIdx.x * BN;

    float acc[8][8];
    #pragma unroll
    for (int m = 0; m < 8; ++m)
        #pragma unroll
        for (int n = 0; n < 8; ++n) acc[m][n] = 0.f;

    for (int k0 = 0; k0 < D; k0 += BK) {
        if (TRANSA) {
            // operand is A^T, A stored K x M: As[k][i] = A[(k0+k)*D + row0+i]
            #pragma unroll
            for (int it = 0; it < 2; ++it) {
                int idx = tid + it * 256;
                int k = idx >> 5, i4 = (idx & 31) << 2;
                float4 t4 = *reinterpret_cast<const float4*>(&A[(size_t)(k0 + k) * D + row0 + i4]);
                *reinterpret_cast<float4*>(&As[k][i4]) = t4;
            }
        } else {
            // A stored M x K: transpose on store
            #pragma unroll
            for (int it = 0; it < 2; ++it) {
                int r = (tid >> 2) + it * 64;
                int c4 = (tid & 3) << 2;
                float4 t4 = *reinterpret_cast<const float4*>(&A[(size_t)(row0 + r) * D + k0 + c4]);
                As[c4 + 0][r] = t4.x;
                As[c4 + 1][r] = t4.y;
                As[c4 + 2][r] = t4.z;
                As[c4 + 3][r] = t4.w;
            }
        }
        #pragma unroll
        for (int it = 0; it < 2; ++it) {
            int idx = tid + it * 256;
            int k = idx >> 5, j4 = (idx & 31) << 2;
            float4 t4 = *reinterpret_cast<const float4*>(&B[(size_t)(k0 + k) * D + col0 + j4]);
            *reinterpret_cast<float4*>(&Bs[k][j4]) = t4;
        }
        __syncthreads();

        #pragma unroll
        for (int k = 0; k < BK; ++k) {
            float a[8], b[8];
            *reinterpret_cast<float4*>(&a[0]) = *reinterpret_cast<const float4*>(&As[k][ty * 8]);
            *reinterpret_cast<float4*>(&a[4]) = *reinterpret_cast<const float4*>(&As[k][ty * 8 + 4]);
            *reinterpret_cast<float4*>(&b[0]) = *reinterpret_cast<const float4*>(&Bs[k][tx * 8]);
            *reinterpret_cast<float4*>(&b[4]) = *reinterpret_cast<const float4*>(&Bs[k][tx * 8 + 4]);
            #pragma unroll
            for (int m = 0; m < 8; ++m)
                #pragma unroll
                for (int n = 0; n < 8; ++n)
                    acc[m][n] = fmaf(a[m], b[n], acc[m][n]);
        }
        __syncthreads();
    }

    #pragma unroll
    for (int m = 0; m < 8; ++m) {
        int r = row0 + ty * 8 + m;
        #pragma unroll
        for (int n = 0; n < 8; n += 4) {
            int c = col0 + tx * 8 + n;
            float4 o;
            o.x = acc[m][n]; o.y = acc[m][n + 1]; o.z = acc[m][n + 2]; o.w = acc[m][n + 3];
            if (EPI == 1) {
                float4 e = *reinterpret_cast<const float4*>(&E[(size_t)r * D + c]);
                o.x = 1.5f * e.x - 0.5f * o.x;
                o.y = 1.5f * e.y - 0.5f * o.y;
                o.z = 1.5f * e.z - 0.5f * o.z;
                o.w = 1.5f * e.w - 0.5f * o.w;
            } else if (EPI == 2) {
                float4 e = *reinterpret_cast<const float4*>(&E[c]);
                o.x += e.x; o.y += e.y; o.z += e.z; o.w += e.w;
            }
            *reinterpret_cast<float4*>(&C[(size_t)r * D + c]) = o;
        }
    }
}

// ---------------- host orchestration ----------------
extern "C" void kernel_launch(void* const* d_in, const int* in_sizes, int n_in,
                              void* d_out, int out_size) {
    const float* x    = (const float*)d_in[0];   // [TOKENS, D]
    const float* W    = (const float*)d_in[1];   // [D, D]
    const float* bias = (const float*)d_in[2];   // [D]
    float* out = (float*)d_out;                  // [TOKENS, D]

    float *theta, *tmpT, *Abuf, *u, *v, *part, *sig;
    cudaGetSymbolAddress((void**)&theta, g_theta);
    cudaGetSymbolAddress((void**)&tmpT,  g_tmpT);
    cudaGetSymbolAddress((void**)&Abuf,  g_A);
    cudaGetSymbolAddress((void**)&u,     g_u);
    cudaGetSymbolAddress((void**)&v,     g_v);
    cudaGetSymbolAddress((void**)&part,  g_part);
    cudaGetSymbolAddress((void**)&sig,   g_sigma);

    // ---- power iteration (sigma only needs to be within [sigma1/sqrt(3), sigma1]) ----
    colmean_k<<<D / 256, 256>>>(W, u);
    normalize_k<<<1, 1024>>>(u, nullptr);
    for (int it = 0; it < POW_ITERS; ++it) {
        matvec_row_k<<<D / 8, 256>>>(W, u, v);
        normalize_k<<<1, 1024>>>(v, nullptr);
        matvec_col_part_k<<<dim3(D / 256, 16), 256>>>(W, v, part);
        part_reduce_k<<<D / 256, 256>>>(part, u);
        normalize_k<<<1, 1024>>>(u, nullptr);
    }
    // sigma = ||W @ u||
    matvec_row_k<<<D / 8, 256>>>(W, u, v);
    normalize_k<<<1, 1024>>>(v, sig);

    // theta0 = W / (sigma + 1e-5)
    scale_k<<<(D * D / 4) / 256, 256>>>(W, theta, sig);

    // ---- Bjorck / Newton-Schulz: theta <- 1.5 theta - 0.5 theta (theta^T theta) ----
    dim3 gsq(D / BN, D / BM);
    float* cur = theta;
    float* alt = tmpT;
    for (int it = 0; it < BJ_ITERS; ++it) {
        sgemm_k<true,  0><<<gsq, 256>>>(cur, cur, Abuf, nullptr);   // A = cur^T cur
        sgemm_k<false, 1><<<gsq, 256>>>(cur, Abuf, alt, cur);       // alt = 1.5 cur - 0.5 cur A
        float* t = cur; cur = alt; alt = t;
    }

    // ---- out = x @ theta + bias ----
    dim3 gout(D / BN, TOKENS / BM);
    sgemm_k<false, 2><<<gout, 256>>>(x, cur, out, bias);
}

// round 4
// speedup vs baseline: 4.1994x; 4.1994x over previous
#include <cuda_runtime.h>
#include <cuda_bf16.h>
#include <math.h>
#include <stdint.h>

// Problem dims (fixed by the dataset)
#define D      2048
#define TOKENS 8192

#define POW_ITERS 12
#define NQ 9        // quintic Newton-Schulz iterations
#define NC 5        // cubic polish iterations (NQ+NC must be even)

// GEMM tiling: CTA 128x128, 8 warps (2 x 4), warp tile 64x32, K-chunk 32
#define KC 32
#define KSTAGES (D / KC)         // 64
#define RS 40                    // smem row stride in bf16 (80B, 16B-aligned, ldmatrix conflict-free)
#define MAT_BYTES (128 * RS * 2) // 10240
#define STG_BYTES (4 * MAT_BYTES) // Ah | Al | Bh | Bl = 40960
#define NSTAGE 4
#define SMEM_TOT (NSTAGE * STG_BYTES)  // 163840

typedef __nv_bfloat16 bf16;

// ---------------- scratch (no allocs allowed) ----------------
__device__ __align__(16) bf16 g_th [2][(size_t)D * D];
__device__ __align__(16) bf16 g_tl [2][(size_t)D * D];
__device__ __align__(16) bf16 g_tTh[2][(size_t)D * D];
__device__ __align__(16) bf16 g_tTl[2][(size_t)D * D];
__device__ __align__(16) bf16 g_Gh[(size_t)D * D];
__device__ __align__(16) bf16 g_Gl[(size_t)D * D];
__device__ __align__(16) bf16 g_Hh[(size_t)D * D];
__device__ __align__(16) bf16 g_Hl[(size_t)D * D];
__device__ __align__(16) bf16 g_xh[(size_t)TOKENS * D];
__device__ __align__(16) bf16 g_xl[(size_t)TOKENS * D];
__device__ __align__(16) float g_u[D];
__device__ __align__(16) float g_v[D];
__device__ __align__(16) float g_part[16 * D];
__device__ float g_sigma;

// ---------------- PTX helpers (base ISA only: sm_80+) ----------------
static __device__ __forceinline__ uint32_t s2u(const void* p) {
    uint32_t a;
    asm("{ .reg .u64 t; cvta.to.shared.u64 t, %1; cvt.u32.u64 %0, t; }" : "=r"(a) : "l"(p));
    return a;
}
static __device__ __forceinline__ void cp16(uint32_t dst, const void* src) {
    asm volatile("cp.async.cg.shared.global [%0], [%1], 16;" :: "r"(dst), "l"(src));
}
static __device__ __forceinline__ void cp_commit() {
    asm volatile("cp.async.commit_group;" ::: "memory");
}
template<int N> static __device__ __forceinline__ void cp_wait() {
    asm volatile("cp.async.wait_group %0;" :: "n"(N) : "memory");
}
#define LDSM_X4(r, addr) \
    asm volatile("ldmatrix.sync.aligned.m8n8.x4.shared.b16 {%0,%1,%2,%3}, [%4];" \
        : "=r"((r)[0]), "=r"((r)[1]), "=r"((r)[2]), "=r"((r)[3]) : "r"(addr))
#define MMA16816(d, a, b) \
    asm volatile("mma.sync.aligned.m16n8k16.row.col.f32.bf16.bf16.f32 " \
        "{%0,%1,%2,%3}, {%4,%5,%6,%7}, {%8,%9}, {%0,%1,%2,%3};" \
        : "+f"((d)[0]), "+f"((d)[1]), "+f"((d)[2]), "+f"((d)[3]) \
        : "r"((a)[0]), "r"((a)[1]), "r"((a)[2]), "r"((a)[3]), "r"((b)[0]), "r"((b)[1]))

static __device__ __forceinline__ void split2(float v, bf16& h, bf16& l) {
    h = __float2bfloat16(v);
    l = __float2bfloat16(v - __bfloat162float(h));
}

// ---------------- small vector kernels (power iteration) ----------------
__global__ void colmean_k(const float* __restrict__ W, float* __restrict__ u) {
    int j = blockIdx.x * blockDim.x + threadIdx.x;
    float s = 0.f;
    for (int i = 0; i < D; ++i) s += W[(size_t)i * D + j];
    u[j] = s * (1.0f / D);
}

__global__ void normalize_k(float* __restrict__ v, float* __restrict__ out_norm) {
    __shared__ float red[1024];
    int t = threadIdx.x;
    float s = 0.f;
    for (int i = t; i < D; i += 1024) { float x = v[i]; s += x * x; }
    red[t] = s;
    __syncthreads();
    for (int o = 512; o > 0; o >>= 1) {
        if (t < o) red[t] += red[t + o];
        __syncthreads();
    }
    if (t == 0) {
        float nrm = sqrtf(red[0]);
        if (out_norm) *out_norm = nrm;
        red[0] = 1.0f / (nrm + 1e-10f);
    }
    __syncthreads();
    float iv = red[0];
    for (int i = t; i < D; i += 1024) v[i] *= iv;
}

__global__ void matvec_row_k(const float* __restrict__ W, const float* __restrict__ u,
                             float* __restrict__ y) {
    int warp = threadIdx.x >> 5, lane = threadIdx.x & 31;
    int row = blockIdx.x * 8 + warp;
    const float* wr = W + (size_t)row * D;
    float s = 0.f;
    for (int c = lane; c < D; c += 32) s += wr[c] * u[c];
    #pragma unroll
    for (int o = 16; o > 0; o >>= 1) s += __shfl_xor_sync(0xffffffffu, s, o);
    if (lane == 0) y[row] = s;
}

__global__ void matvec_col_part_k(const float* __restrict__ W, const float* __restrict__ v,
                                  float* __restrict__ part) {
    int j = blockIdx.x * 256 + threadIdx.x;
    int r0 = blockIdx.y * 128;
    float s = 0.f;
    #pragma unroll 4
    for (int i = 0; i < 128; ++i) s += v[r0 + i] * W[(size_t)(r0 + i) * D + j];
    part[blockIdx.y * D + j] = s;
}

__global__ void part_reduce_k(const float* __restrict__ part, float* __restrict__ z) {
    int j = blockIdx.x * 256 + threadIdx.x;
    float s = 0.f;
    #pragma unroll
    for (int c = 0; c < 16; ++c) s += part[c * D + j];
    z[j] = s;
}

// ---------------- prep: theta0 = W/sigma, split hi/lo, both orientations ----------------
__global__ void prep_theta_k(const float* __restrict__ W, const float* __restrict__ sig,
                             bf16* __restrict__ th, bf16* __restrict__ tl,
                             bf16* __restrict__ tTh, bf16* __restrict__ tTl) {
    __shared__ float s[32][33];
    float inv = 1.0f / (*sig + 1e-5f);
    int r = blockIdx.y * 32 + threadIdx.y;
    int c = blockIdx.x * 32 + threadIdx.x;
    float v = W[(size_t)r * D + c] * inv;
    bf16 h, l;
    split2(v, h, l);
    th[(size_t)r * D + c] = h;
    tl[(size_t)r * D + c] = l;
    s[threadIdx.y][threadIdx.x] = v;
    __syncthreads();
    float v2 = s[threadIdx.x][threadIdx.y];
    int r2 = blockIdx.x * 32 + threadIdx.y;
    int c2 = blockIdx.y * 32 + threadIdx.x;
    split2(v2, h, l);
    tTh[(size_t)r2 * D + c2] = h;
    tTl[(size_t)r2 * D + c2] = l;
}

__global__ void split_x_k(const float* __restrict__ x,
                          bf16* __restrict__ xh, bf16* __restrict__ xl) {
    size_t i = (size_t)blockIdx.x * 256 + threadIdx.x;
    bf16 h, l;
    split2(x[i], h, l);
    xh[i] = h; xl[i] = l;
}

// ---------------- split-bf16 mma.sync GEMM ----------------
// C[m][n] = sum_k A[m][k]*B[n][k] with A ~ Ah+Al, B ~ Bh+Bl (hh + hl + lh).
// EPI 0: G-sym  : store split(acc) at transposed address into Oh/Ol (symmetric output)
// EPI 1: AFF    : v = alpha*A[m][n] + beta*acc; store split(v) normal (Oh/Ol) + transposed (OTh/OTl)
// EPI 2: OUT    : Of = acc + bias[n]
// EPI 3: AFFSYM : v = alpha*A[m][n] + beta*acc; store split(v) transposed only (Oh/Ol; symmetric)
static __device__ __forceinline__ void load_stage(
    uint32_t sb, int buf, int kc, int tid, int row0, int col0,
    const bf16* __restrict__ Ah, const bf16* __restrict__ Al,
    const bf16* __restrict__ Bh, const bf16* __restrict__ Bl) {
    uint32_t base = sb + buf * STG_BYTES;
    int r_lo = tid >> 2;         // 0..63
    int c = tid & 3;             // 16B chunk within 64B of row data
    const bf16* mats[4] = { Ah, Al, Bh, Bl };
    #pragma unroll
    for (int it = 0; it < 8; ++it) {
        int mat = it >> 1;
        int r = (it & 1) * 64 + r_lo;
        int base_row = (mat < 2) ? row0 : col0;
        uint32_t dst = base + mat * MAT_BYTES + r * (RS * 2) + c * 16;
        const bf16* src = mats[mat] + (size_t)(base_row + r) * D + kc + c * 8;
        cp16(dst, src);
    }
}

template<int EPI>
__global__ void __launch_bounds__(256, 1) mgemm_k(
    const bf16* __restrict__ Ah, const bf16* __restrict__ Al,
    const bf16* __restrict__ Bh, const bf16* __restrict__ Bl,
    bf16* __restrict__ Oh, bf16* __restrict__ Ol,
    bf16* __restrict__ OTh, bf16* __restrict__ OTl,
    const float* __restrict__ bias, float* __restrict__ Of,
    float alpha, float beta) {
    extern __shared__ char smem[];
    const uint32_t sb = s2u(smem);
    const int tid = threadIdx.x, wid = tid >> 5, lane = tid & 31;
    const int warp_m = wid & 1, warp_n = wid >> 1;
    const int row0 = blockIdx.y * 128, col0 = blockIdx.x * 128;

    // per-lane ldmatrix byte offsets within a tile
    uint32_t aoff[4], boff[2];
    #pragma unroll
    for (int mf = 0; mf < 4; ++mf)
        aoff[mf] = (uint32_t)((warp_m * 64 + mf * 16 + (lane & 15)) * (RS * 2) + (lane >> 4) * 16);
    #pragma unroll
    for (int n2 = 0; n2 < 2; ++n2)
        boff[n2] = (uint32_t)((warp_n * 32 + n2 * 16 + (lane & 7) + ((lane >> 4) & 1) * 8) * (RS * 2)
                              + ((lane >> 3) & 1) * 16);

    float acc[4][4][4];
    #pragma unroll
    for (int mf = 0; mf < 4; ++mf)
        #pragma unroll
        for (int nf = 0; nf < 4; ++nf)
            #pragma unroll
            for (int i = 0; i < 4; ++i) acc[mf][nf][i] = 0.f;

    // prefetch 3 stages
    #pragma unroll
    for (int s = 0; s < 3; ++s) {
        load_stage(sb, s, s * KC, tid, row0, col0, Ah, Al, Bh, Bl);
        cp_commit();
    }

    for (int s = 0; s < KSTAGES; ++s) {
        cp_wait<2>();
        __syncthreads();
        if (s + 3 < KSTAGES)
            load_stage(sb, (s + 3) & 3, (s + 3) * KC, tid, row0, col0, Ah, Al, Bh, Bl);
        cp_commit();

        uint32_t abase = sb + (s & 3) * STG_BYTES;
        uint32_t bbase = abase + 2 * MAT_BYTES;
        #pragma unroll
        for (int s2 = 0; s2 < 2; ++s2) {
            uint32_t ah[4][4], al[4][4], bh[8], bl[8];
            uint32_t ko = s2 * 32;
            #pragma unroll
            for (int mf = 0; mf < 4; ++mf) LDSM_X4(ah[mf], abase + aoff[mf] + ko);
            #pragma unroll
            for (int mf = 0; mf < 4; ++mf) LDSM_X4(al[mf], abase + MAT_BYTES + aoff[mf] + ko);
            #pragma unroll
            for (int n2 = 0; n2 < 2; ++n2) LDSM_X4(&bh[n2 * 4], bbase + boff[n2] + ko);
            #pragma unroll
            for (int n2 = 0; n2 < 2; ++n2) LDSM_X4(&bl[n2 * 4], bbase + MAT_BYTES + boff[n2] + ko);
            #pragma unroll
            for (int mf = 0; mf < 4; ++mf)
                #pragma unroll
                for (int nf = 0; nf < 4; ++nf) {
                    MMA16816(acc[mf][nf], ah[mf], &bh[nf * 2]);
                    MMA16816(acc[mf][nf], ah[mf], &bl[nf * 2]);
                    MMA16816(acc[mf][nf], al[mf], &bh[nf * 2]);
                }
        }
    }
    __syncthreads();   // pipeline done; smem reused as epilogue staging

    // ---- stage acc into smem: per warp a 64x33 fp32 tile ----
    float* stg = (float*)smem + wid * (64 * 33);
    #pragma unroll
    for (int mf = 0; mf < 4; ++mf)
        #pragma unroll
        for (int nf = 0; nf < 4; ++nf) {
            int r = mf * 16 + (lane >> 2);
            int c = nf * 8 + 2 * (lane & 3);
            stg[r * 33 + c]           = acc[mf][nf][0];
            stg[r * 33 + c + 1]       = acc[mf][nf][1];
            stg[(r + 8) * 33 + c]     = acc[mf][nf][2];
            stg[(r + 8) * 33 + c + 1] = acc[mf][nf][3];
        }
    __syncwarp();

    const int rb = row0 + warp_m * 64;
    const int cb = col0 + warp_n * 32;

    if (EPI == 0) {
        #pragma unroll 4
        for (int c = 0; c < 32; ++c)
            #pragma unroll
            for (int h = 0; h < 2; ++h) {
                float v = stg[(lane + 32 * h) * 33 + c];
                bf16 hh, ll; split2(v, hh, ll);
                size_t a = (size_t)(cb + c) * D + rb + lane + 32 * h;
                Oh[a] = hh; Ol[a] = ll;
            }
    } else if (EPI == 2) {
        float bv = bias[cb + lane];
        #pragma unroll 4
        for (int r = 0; r < 64; ++r)
            Of[(size_t)(rb + r) * D + cb + lane] = stg[r * 33 + lane] + bv;
    } else {   // EPI 1 / 3: affine v = alpha*A + beta*acc
        #pragma unroll 4
        for (int r = 0; r < 64; ++r) {
            size_t a = (size_t)(rb + r) * D + cb + lane;
            float tv = __bfloat162float(Ah[a]) + __bfloat162float(Al[a]);
            float v = alpha * tv + beta * stg[r * 33 + lane];
            stg[r * 33 + lane] = v;
            if (EPI == 1) {
                bf16 hh, ll; split2(v, hh, ll);
                Oh[a] = hh; Ol[a] = ll;
            }
        }
        __syncwarp();
        bf16* Th = (EPI == 1) ? OTh : Oh;
        bf16* Tl = (EPI == 1) ? OTl : Ol;
        #pragma unroll 4
        for (int c = 0; c < 32; ++c)
            #pragma unroll
            for (int h = 0; h < 2; ++h) {
                float v = stg[(lane + 32 * h) * 33 + c];
                bf16 hh, ll; split2(v, hh, ll);
                size_t a = (size_t)(cb + c) * D + rb + lane + 32 * h;
                Th[a] = hh; Tl[a] = ll;
            }
    }
}

// ---------------- host orchestration ----------------
extern "C" void kernel_launch(void* const* d_in, const int* in_sizes, int n_in,
                              void* d_out, int out_size) {
    const float* x    = (const float*)d_in[0];   // [TOKENS, D]
    const float* W    = (const float*)d_in[1];   // [D, D]
    const float* bias = (const float*)d_in[2];   // [D]
    float* out = (float*)d_out;                  // [TOKENS, D]

    cudaFuncSetAttribute(mgemm_k<0>, cudaFuncAttributeMaxDynamicSharedMemorySize, SMEM_TOT);
    cudaFuncSetAttribute(mgemm_k<1>, cudaFuncAttributeMaxDynamicSharedMemorySize, SMEM_TOT);
    cudaFuncSetAttribute(mgemm_k<2>, cudaFuncAttributeMaxDynamicSharedMemorySize, SMEM_TOT);
    cudaFuncSetAttribute(mgemm_k<3>, cudaFuncAttributeMaxDynamicSharedMemorySize, SMEM_TOT);

    bf16 *thB, *tlB, *tThB, *tTlB, *Gh, *Gl, *Hh, *Hl, *xh, *xl;
    float *u, *v, *part, *sig;
    cudaGetSymbolAddress((void**)&thB,  g_th);
    cudaGetSymbolAddress((void**)&tlB,  g_tl);
    cudaGetSymbolAddress((void**)&tThB, g_tTh);
    cudaGetSymbolAddress((void**)&tTlB, g_tTl);
    cudaGetSymbolAddress((void**)&Gh,   g_Gh);
    cudaGetSymbolAddress((void**)&Gl,   g_Gl);
    cudaGetSymbolAddress((void**)&Hh,   g_Hh);
    cudaGetSymbolAddress((void**)&Hl,   g_Hl);
    cudaGetSymbolAddress((void**)&xh,   g_xh);
    cudaGetSymbolAddress((void**)&xl,   g_xl);
    cudaGetSymbolAddress((void**)&u,    g_u);
    cudaGetSymbolAddress((void**)&v,    g_v);
    cudaGetSymbolAddress((void**)&part, g_part);
    cudaGetSymbolAddress((void**)&sig,  g_sigma);

    const size_t DD = (size_t)D * D;
    bf16* th[2]  = { thB,  thB  + DD };
    bf16* tl[2]  = { tlB,  tlB  + DD };
    bf16* tTh[2] = { tThB, tThB + DD };
    bf16* tTl[2] = { tTlB, tTlB + DD };

    // ---- power iteration (sigma within a few % of sigma1) ----
    colmean_k<<<D / 256, 256>>>(W, u);
    normalize_k<<<1, 1024>>>(u, nullptr);
    for (int it = 0; it < POW_ITERS; ++it) {
        matvec_row_k<<<D / 8, 256>>>(W, u, v);
        normalize_k<<<1, 1024>>>(v, nullptr);
        matvec_col_part_k<<<dim3(D / 256, 16), 256>>>(W, v, part);
        part_reduce_k<<<D / 256, 256>>>(part, u);
        normalize_k<<<1, 1024>>>(u, nullptr);
    }
    matvec_row_k<<<D / 8, 256>>>(W, u, v);
    normalize_k<<<1, 1024>>>(v, sig);         // sigma = ||W u||

    // ---- theta0 = W/sigma split bf16 both orientations; split x ----
    prep_theta_k<<<dim3(64, 64), dim3(32, 32)>>>(W, sig, th[0], tl[0], tTh[0], tTl[0]);
    split_x_k<<<(unsigned)((size_t)TOKENS * D / 256), 256>>>(x, xh, xl);

    const float a5 = 3.4445f, b5 = -4.7750f, c5 = 2.0315f;
    dim3 gsq(D / 128, D / 128);               // 16 x 16

    // ---- quintic Newton-Schulz: theta <- a*theta + theta*(b*G + c*G^2), G = theta^T theta ----
    for (int it = 0; it < NQ; ++it) {
        int p = it & 1, q = p ^ 1;
        mgemm_k<0><<<gsq, 256, SMEM_TOT>>>(tTh[p], tTl[p], tTh[p], tTl[p],
                                           Gh, Gl, nullptr, nullptr, nullptr, nullptr, 0.f, 0.f);
        mgemm_k<3><<<gsq, 256, SMEM_TOT>>>(Gh, Gl, Gh, Gl,
                                           Hh, Hl, nullptr, nullptr, nullptr, nullptr, b5, c5);
        mgemm_k<1><<<gsq, 256, SMEM_TOT>>>(th[p], tl[p], Hh, Hl,
                                           th[q], tl[q], tTh[q], tTl[q], nullptr, nullptr, a5, 1.0f);
    }
    // ---- cubic polish: theta <- 1.5*theta - 0.5*theta*G ----
    for (int it = NQ; it < NQ + NC; ++it) {
        int p = it & 1, q = p ^ 1;
        mgemm_k<0><<<gsq, 256, SMEM_TOT>>>(tTh[p], tTl[p], tTh[p], tTl[p],
                                           Gh, Gl, nullptr, nullptr, nullptr, nullptr, 0.f, 0.f);
        mgemm_k<1><<<gsq, 256, SMEM_TOT>>>(th[p], tl[p], Gh, Gl,
                                           th[q], tl[q], tTh[q], tTl[q], nullptr, nullptr, 1.5f, -0.5f);
    }
    // (NQ + NC) even -> final theta in set 0

    // ---- out = x @ theta + bias ----
    dim3 gf(D / 128, TOKENS / 128);           // 16 x 64
    mgemm_k<2><<<gf, 256, SMEM_TOT>>>(xh, xl, tTh[0], tTl[0],
                                      nullptr, nullptr, nullptr, nullptr, bias, out, 0.f, 0.f);
}

// round 5
// speedup vs baseline: 6.3598x; 1.5144x over previous
#include <cuda_runtime.h>
#include <cuda_bf16.h>
#include <math.h>
#include <stdint.h>

// Problem dims (fixed by the dataset)
#define D      2048
#define TOKENS 8192

#define POW_ITERS 12
#define NQ 8        // quintic Newton-Schulz iterations
#define NC 4        // cubic polish iterations (NQ+NC even -> result in set 0)

// GEMM tiling: CTA 128x128, 8 warps (2 x 4), warp tile 64x32, K-chunk 32
#define KC 32
#define KSTAGES (D / KC)         // 64
#define RS 40                    // smem row stride in bf16 (80B, 16B-aligned, ldmatrix conflict-free)
#define MAT_BYTES (128 * RS * 2) // 10240
#define STG_BYTES (4 * MAT_BYTES) // Ah | Al | Bh | Bl = 40960
#define NSTAGE 4
#define SMEM_TOT (NSTAGE * STG_BYTES)  // 163840

#define NTILE 16                 // D/128
#define NTRI  (NTILE * (NTILE + 1) / 2)   // 136 upper-triangular tiles

typedef __nv_bfloat16 bf16;

// ---------------- scratch (no allocs allowed) ----------------
__device__ __align__(16) bf16 g_th [2][(size_t)D * D];
__device__ __align__(16) bf16 g_tl [2][(size_t)D * D];
__device__ __align__(16) bf16 g_tTh[2][(size_t)D * D];
__device__ __align__(16) bf16 g_tTl[2][(size_t)D * D];
__device__ __align__(16) bf16 g_Gh[(size_t)D * D];
__device__ __align__(16) bf16 g_Gl[(size_t)D * D];
__device__ __align__(16) bf16 g_Hh[(size_t)D * D];
__device__ __align__(16) bf16 g_Hl[(size_t)D * D];
__device__ __align__(16) bf16 g_xh[(size_t)TOKENS * D];
__device__ __align__(16) bf16 g_xl[(size_t)TOKENS * D];
__device__ __align__(16) float g_u[D];
__device__ __align__(16) float g_v[D];
__device__ __align__(16) float g_part[16 * D];
__device__ float g_sigma;

// ---------------- PTX helpers (base ISA only: sm_80+) ----------------
static __device__ __forceinline__ uint32_t s2u(const void* p) {
    uint32_t a;
    asm("{ .reg .u64 t; cvta.to.shared.u64 t, %1; cvt.u32.u64 %0, t; }" : "=r"(a) : "l"(p));
    return a;
}
static __device__ __forceinline__ void cp16(uint32_t dst, const void* src) {
    asm volatile("cp.async.cg.shared.global [%0], [%1], 16;" :: "r"(dst), "l"(src));
}
static __device__ __forceinline__ void cp_commit() {
    asm volatile("cp.async.commit_group;" ::: "memory");
}
template<int N> static __device__ __forceinline__ void cp_wait() {
    asm volatile("cp.async.wait_group %0;" :: "n"(N) : "memory");
}
#define LDSM_X4(r, addr) \
    asm volatile("ldmatrix.sync.aligned.m8n8.x4.shared.b16 {%0,%1,%2,%3}, [%4];" \
        : "=r"((r)[0]), "=r"((r)[1]), "=r"((r)[2]), "=r"((r)[3]) : "r"(addr))
#define MMA16816(d, a, b) \
    asm volatile("mma.sync.aligned.m16n8k16.row.col.f32.bf16.bf16.f32 " \
        "{%0,%1,%2,%3}, {%4,%5,%6,%7}, {%8,%9}, {%0,%1,%2,%3};" \
        : "+f"((d)[0]), "+f"((d)[1]), "+f"((d)[2]), "+f"((d)[3]) \
        : "r"((a)[0]), "r"((a)[1]), "r"((a)[2]), "r"((a)[3]), "r"((b)[0]), "r"((b)[1]))

static __device__ __forceinline__ void split2(float v, bf16& h, bf16& l) {
    h = __float2bfloat16(v);
    l = __float2bfloat16(v - __bfloat162float(h));
}

// ---------------- small vector kernels (power iteration) ----------------
__global__ void colmean_k(const float* __restrict__ W, float* __restrict__ u) {
    int j = blockIdx.x * blockDim.x + threadIdx.x;
    float s = 0.f;
    for (int i = 0; i < D; ++i) s += W[(size_t)i * D + j];
    u[j] = s * (1.0f / D);
}

__global__ void normalize_k(float* __restrict__ v, float* __restrict__ out_norm) {
    __shared__ float red[1024];
    int t = threadIdx.x;
    float s = 0.f;
    for (int i = t; i < D; i += 1024) { float x = v[i]; s += x * x; }
    red[t] = s;
    __syncthreads();
    for (int o = 512; o > 0; o >>= 1) {
        if (t < o) red[t] += red[t + o];
        __syncthreads();
    }
    if (t == 0) {
        float nrm = sqrtf(red[0]);
        if (out_norm) *out_norm = nrm;
        red[0] = 1.0f / (nrm + 1e-10f);
    }
    __syncthreads();
    float iv = red[0];
    for (int i = t; i < D; i += 1024) v[i] *= iv;
}

__global__ void matvec_row_k(const float* __restrict__ W, const float* __restrict__ u,
                             float* __restrict__ y) {
    int warp = threadIdx.x >> 5, lane = threadIdx.x & 31;
    int row = blockIdx.x * 8 + warp;
    const float* wr = W + (size_t)row * D;
    float s = 0.f;
    for (int c = lane; c < D; c += 32) s += wr[c] * u[c];
    #pragma unroll
    for (int o = 16; o > 0; o >>= 1) s += __shfl_xor_sync(0xffffffffu, s, o);
    if (lane == 0) y[row] = s;
}

__global__ void matvec_col_part_k(const float* __restrict__ W, const float* __restrict__ v,
                                  float* __restrict__ part) {
    int j = blockIdx.x * 256 + threadIdx.x;
    int r0 = blockIdx.y * 128;
    float s = 0.f;
    #pragma unroll 4
    for (int i = 0; i < 128; ++i) s += v[r0 + i] * W[(size_t)(r0 + i) * D + j];
    part[blockIdx.y * D + j] = s;
}

__global__ void part_reduce_k(const float* __restrict__ part, float* __restrict__ z) {
    int j = blockIdx.x * 256 + threadIdx.x;
    float s = 0.f;
    #pragma unroll
    for (int c = 0; c < 16; ++c) s += part[c * D + j];
    z[j] = s;
}

// ---------------- prep: theta0 = W/sigma, split hi/lo, both orientations ----------------
__global__ void prep_theta_k(const float* __restrict__ W, const float* __restrict__ sig,
                             bf16* __restrict__ th, bf16* __restrict__ tl,
                             bf16* __restrict__ tTh, bf16* __restrict__ tTl) {
    __shared__ float s[32][33];
    float inv = 1.0f / (*sig + 1e-5f);
    int r = blockIdx.y * 32 + threadIdx.y;
    int c = blockIdx.x * 32 + threadIdx.x;
    float v = W[(size_t)r * D + c] * inv;
    bf16 h, l;
    split2(v, h, l);
    th[(size_t)r * D + c] = h;
    tl[(size_t)r * D + c] = l;
    s[threadIdx.y][threadIdx.x] = v;
    __syncthreads();
    float v2 = s[threadIdx.x][threadIdx.y];
    int r2 = blockIdx.x * 32 + threadIdx.y;
    int c2 = blockIdx.y * 32 + threadIdx.x;
    split2(v2, h, l);
    tTh[(size_t)r2 * D + c2] = h;
    tTl[(size_t)r2 * D + c2] = l;
}

__global__ void split_x_k(const float* __restrict__ x,
                          bf16* __restrict__ xh, bf16* __restrict__ xl) {
    size_t i = (size_t)blockIdx.x * 256 + threadIdx.x;
    bf16 h, l;
    split2(x[i], h, l);
    xh[i] = h; xl[i] = l;
}

// ---------------- split-bf16 mma.sync GEMM ----------------
// C[m][n] = sum_k A[m][k]*B[n][k] with A ~ Ah+Al, B ~ Bh+Bl (hh + hl + lh).
// EPI 0: G-sym  : triangular 1D grid; store split(acc) at BOTH (r,c) and (c,r) in Oh/Ol
// EPI 3: H-sym  : triangular 1D grid; v = alpha*A[m][n] + beta*acc; store both orientations in Oh/Ol
// EPI 1: update : full grid; v = alpha*A[m][n] + beta*acc; store normal Oh/Ol + transposed OTh/OTl
// EPI 2: out    : full grid; Of = acc + bias[n]
static __device__ __forceinline__ void load_stage(
    uint32_t sb, int buf, int kc, int tid, int row0, int col0,
    const bf16* __restrict__ Ah, const bf16* __restrict__ Al,
    const bf16* __restrict__ Bh, const bf16* __restrict__ Bl) {
    uint32_t base = sb + buf * STG_BYTES;
    int r_lo = tid >> 2;         // 0..63
    int c = tid & 3;             // 16B chunk within 64B of row data
    const bf16* mats[4] = { Ah, Al, Bh, Bl };
    #pragma unroll
    for (int it = 0; it < 8; ++it) {
        int mat = it >> 1;
        int r = (it & 1) * 64 + r_lo;
        int base_row = (mat < 2) ? row0 : col0;
        uint32_t dst = base + mat * MAT_BYTES + r * (RS * 2) + c * 16;
        const bf16* src = mats[mat] + (size_t)(base_row + r) * D + kc + c * 8;
        cp16(dst, src);
    }
}

template<int EPI>
__global__ void __launch_bounds__(256, 1) mgemm_k(
    const bf16* __restrict__ Ah, const bf16* __restrict__ Al,
    const bf16* __restrict__ Bh, const bf16* __restrict__ Bl,
    bf16* __restrict__ Oh, bf16* __restrict__ Ol,
    bf16* __restrict__ OTh, bf16* __restrict__ OTl,
    const float* __restrict__ bias, float* __restrict__ Of,
    float alpha, float beta) {
    extern __shared__ char smem[];
    const uint32_t sb = s2u(smem);
    const int tid = threadIdx.x, wid = tid >> 5, lane = tid & 31;
    const int warp_m = wid & 1, warp_n = wid >> 1;

    int row0, col0;
    if (EPI == 0 || EPI == 3) {
        // map linear block -> upper-triangular tile (bi <= bj)
        int b = blockIdx.x, bi = 0;
        #pragma unroll 1
        while (b >= (NTILE - bi)) { b -= (NTILE - bi); ++bi; }
        row0 = bi * 128;
        col0 = (bi + b) * 128;
    } else {
        row0 = blockIdx.y * 128;
        col0 = blockIdx.x * 128;
    }

    // per-lane ldmatrix byte offsets within a tile
    uint32_t aoff[4], boff[2];
    #pragma unroll
    for (int mf = 0; mf < 4; ++mf)
        aoff[mf] = (uint32_t)((warp_m * 64 + mf * 16 + (lane & 15)) * (RS * 2) + (lane >> 4) * 16);
    #pragma unroll
    for (int n2 = 0; n2 < 2; ++n2)
        boff[n2] = (uint32_t)((warp_n * 32 + n2 * 16 + (lane & 7) + ((lane >> 4) & 1) * 8) * (RS * 2)
                              + ((lane >> 3) & 1) * 16);

    float acc[4][4][4];
    #pragma unroll
    for (int mf = 0; mf < 4; ++mf)
        #pragma unroll
        for (int nf = 0; nf < 4; ++nf)
            #pragma unroll
            for (int i = 0; i < 4; ++i) acc[mf][nf][i] = 0.f;

    // prefetch 3 stages
    #pragma unroll
    for (int s = 0; s < 3; ++s) {
        load_stage(sb, s, s * KC, tid, row0, col0, Ah, Al, Bh, Bl);
        cp_commit();
    }

    for (int s = 0; s < KSTAGES; ++s) {
        cp_wait<2>();
        __syncthreads();
        if (s + 3 < KSTAGES)
            load_stage(sb, (s + 3) & 3, (s + 3) * KC, tid, row0, col0, Ah, Al, Bh, Bl);
        cp_commit();

        uint32_t abase = sb + (s & 3) * STG_BYTES;
        uint32_t bbase = abase + 2 * MAT_BYTES;
        #pragma unroll
        for (int s2 = 0; s2 < 2; ++s2) {
            uint32_t ah[4][4], al[4][4], bh[8], bl[8];
            uint32_t ko = s2 * 32;
            #pragma unroll
            for (int mf = 0; mf < 4; ++mf) LDSM_X4(ah[mf], abase + aoff[mf] + ko);
            #pragma unroll
            for (int mf = 0; mf < 4; ++mf) LDSM_X4(al[mf], abase + MAT_BYTES + aoff[mf] + ko);
            #pragma unroll
            for (int n2 = 0; n2 < 2; ++n2) LDSM_X4(&bh[n2 * 4], bbase + boff[n2] + ko);
            #pragma unroll
            for (int n2 = 0; n2 < 2; ++n2) LDSM_X4(&bl[n2 * 4], bbase + MAT_BYTES + boff[n2] + ko);
            #pragma unroll
            for (int mf = 0; mf < 4; ++mf)
                #pragma unroll
                for (int nf = 0; nf < 4; ++nf) {
                    MMA16816(acc[mf][nf], ah[mf], &bh[nf * 2]);
                    MMA16816(acc[mf][nf], ah[mf], &bl[nf * 2]);
                    MMA16816(acc[mf][nf], al[mf], &bh[nf * 2]);
                }
        }
    }
    __syncthreads();   // pipeline done; smem reused as epilogue staging

    // ---- stage acc into smem: per warp a 64x33 fp32 tile ----
    float* stg = (float*)smem + wid * (64 * 33);
    #pragma unroll
    for (int mf = 0; mf < 4; ++mf)
        #pragma unroll
        for (int nf = 0; nf < 4; ++nf) {
            int r = mf * 16 + (lane >> 2);
            int c = nf * 8 + 2 * (lane & 3);
            stg[r * 33 + c]           = acc[mf][nf][0];
            stg[r * 33 + c + 1]       = acc[mf][nf][1];
            stg[(r + 8) * 33 + c]     = acc[mf][nf][2];
            stg[(r + 8) * 33 + c + 1] = acc[mf][nf][3];
        }
    __syncwarp();

    const int rb = row0 + warp_m * 64;
    const int cb = col0 + warp_n * 32;

    if (EPI == 0) {
        // normal orientation
        #pragma unroll 4
        for (int r = 0; r < 64; ++r) {
            float v = stg[r * 33 + lane];
            bf16 hh, ll; split2(v, hh, ll);
            size_t a = (size_t)(rb + r) * D + cb + lane;
            Oh[a] = hh; Ol[a] = ll;
        }
        // mirrored orientation (symmetric output)
        #pragma unroll 4
        for (int c = 0; c < 32; ++c)
            #pragma unroll
            for (int h = 0; h < 2; ++h) {
                float v = stg[(lane + 32 * h) * 33 + c];
                bf16 hh, ll; split2(v, hh, ll);
                size_t a = (size_t)(cb + c) * D + rb + lane + 32 * h;
                Oh[a] = hh; Ol[a] = ll;
            }
    } else if (EPI == 2) {
        float bv = bias[cb + lane];
        #pragma unroll 4
        for (int r = 0; r < 64; ++r)
            Of[(size_t)(rb + r) * D + cb + lane] = stg[r * 33 + lane] + bv;
    } else {   // EPI 1 / 3: affine v = alpha*A + beta*acc, write normal + mirrored
        #pragma unroll 4
        for (int r = 0; r < 64; ++r) {
            size_t a = (size_t)(rb + r) * D + cb + lane;
            float tv = __bfloat162float(Ah[a]) + __bfloat162float(Al[a]);
            float v = alpha * tv + beta * stg[r * 33 + lane];
            stg[r * 33 + lane] = v;
            bf16 hh, ll; split2(v, hh, ll);
            Oh[a] = hh; Ol[a] = ll;
        }
        __syncwarp();
        bf16* Th = (EPI == 1) ? OTh : Oh;
        bf16* Tl = (EPI == 1) ? OTl : Ol;
        #pragma unroll 4
        for (int c = 0; c < 32; ++c)
            #pragma unroll
            for (int h = 0; h < 2; ++h) {
                float v = stg[(lane + 32 * h) * 33 + c];
                bf16 hh, ll; split2(v, hh, ll);
                size_t a = (size_t)(cb + c) * D + rb + lane + 32 * h;
                Th[a] = hh; Tl[a] = ll;
            }
    }
}

// ---------------- host orchestration ----------------
extern "C" void kernel_launch(void* const* d_in, const int* in_sizes, int n_in,
                              void* d_out, int out_size) {
    const float* x    = (const float*)d_in[0];   // [TOKENS, D]
    const float* W    = (const float*)d_in[1];   // [D, D]
    const float* bias = (const float*)d_in[2];   // [D]
    float* out = (float*)d_out;                  // [TOKENS, D]

    cudaFuncSetAttribute(mgemm_k<0>, cudaFuncAttributeMaxDynamicSharedMemorySize, SMEM_TOT);
    cudaFuncSetAttribute(mgemm_k<1>, cudaFuncAttributeMaxDynamicSharedMemorySize, SMEM_TOT);
    cudaFuncSetAttribute(mgemm_k<2>, cudaFuncAttributeMaxDynamicSharedMemorySize, SMEM_TOT);
    cudaFuncSetAttribute(mgemm_k<3>, cudaFuncAttributeMaxDynamicSharedMemorySize, SMEM_TOT);

    bf16 *thB, *tlB, *tThB, *tTlB, *Gh, *Gl, *Hh, *Hl, *xh, *xl;
    float *u, *v, *part, *sig;
    cudaGetSymbolAddress((void**)&thB,  g_th);
    cudaGetSymbolAddress((void**)&tlB,  g_tl);
    cudaGetSymbolAddress((void**)&tThB, g_tTh);
    cudaGetSymbolAddress((void**)&tTlB, g_tTl);
    cudaGetSymbolAddress((void**)&Gh,   g_Gh);
    cudaGetSymbolAddress((void**)&Gl,   g_Gl);
    cudaGetSymbolAddress((void**)&Hh,   g_Hh);
    cudaGetSymbolAddress((void**)&Hl,   g_Hl);
    cudaGetSymbolAddress((void**)&xh,   g_xh);
    cudaGetSymbolAddress((void**)&xl,   g_xl);
    cudaGetSymbolAddress((void**)&u,    g_u);
    cudaGetSymbolAddress((void**)&v,    g_v);
    cudaGetSymbolAddress((void**)&part, g_part);
    cudaGetSymbolAddress((void**)&sig,  g_sigma);

    const size_t DD = (size_t)D * D;
    bf16* th[2]  = { thB,  thB  + DD };
    bf16* tl[2]  = { tlB,  tlB  + DD };
    bf16* tTh[2] = { tThB, tThB + DD };
    bf16* tTl[2] = { tTlB, tTlB + DD };

    // ---- power iteration; direction is scale-invariant, so skip intermediate
    // normalizes (norms grow ~sigma1^2 = 4x/iter; 4^12 ~ 2e7, safe in fp32) ----
    colmean_k<<<D / 256, 256>>>(W, u);
    normalize_k<<<1, 1024>>>(u, nullptr);
    for (int it = 0; it < POW_ITERS; ++it) {
        matvec_row_k<<<D / 8, 256>>>(W, u, v);
        matvec_col_part_k<<<dim3(D / 256, 16), 256>>>(W, v, part);
        part_reduce_k<<<D / 256, 256>>>(part, u);
    }
    normalize_k<<<1, 1024>>>(u, nullptr);
    matvec_row_k<<<D / 8, 256>>>(W, u, v);
    normalize_k<<<1, 1024>>>(v, sig);         // sigma = ||W u||

    // ---- theta0 = W/sigma split bf16 both orientations; split x ----
    prep_theta_k<<<dim3(64, 64), dim3(32, 32)>>>(W, sig, th[0], tl[0], tTh[0], tTl[0]);
    split_x_k<<<(unsigned)((size_t)TOKENS * D / 256), 256>>>(x, xh, xl);

    const float a5 = 3.4445f, b5 = -4.7750f, c5 = 2.0315f;
    dim3 gsq(NTILE, NTILE);                   // full 16 x 16
    dim3 gtri(NTRI);                          // 136 triangular tiles (one wave)

    // ---- quintic Newton-Schulz: theta <- a*theta + theta*(b*G + c*G^2) ----
    for (int it = 0; it < NQ; ++it) {
        int p = it & 1, q = p ^ 1;
        mgemm_k<0><<<gtri, 256, SMEM_TOT>>>(tTh[p], tTl[p], tTh[p], tTl[p],
                                            Gh, Gl, nullptr, nullptr, nullptr, nullptr, 0.f, 0.f);
        mgemm_k<3><<<gtri, 256, SMEM_TOT>>>(Gh, Gl, Gh, Gl,
                                            Hh, Hl, nullptr, nullptr, nullptr, nullptr, b5, c5);
        mgemm_k<1><<<gsq, 256, SMEM_TOT>>>(th[p], tl[p], Hh, Hl,
                                           th[q], tl[q], tTh[q], tTl[q], nullptr, nullptr, a5, 1.0f);
    }
    // ---- cubic polish: theta <- 1.5*theta - 0.5*theta*G ----
    for (int it = NQ; it < NQ + NC; ++it) {
        int p = it & 1, q = p ^ 1;
        mgemm_k<0><<<gtri, 256, SMEM_TOT>>>(tTh[p], tTl[p], tTh[p], tTl[p],
                                            Gh, Gl, nullptr, nullptr, nullptr, nullptr, 0.f, 0.f);
        mgemm_k<1><<<gsq, 256, SMEM_TOT>>>(th[p], tl[p], Gh, Gl,
                                           th[q], tl[q], tTh[q], tTl[q], nullptr, nullptr, 1.5f, -0.5f);
    }
    // (NQ + NC) even -> final theta in set 0

    // ---- out = x @ theta + bias ----
    dim3 gf(NTILE, TOKENS / 128);             // 16 x 64
    mgemm_k<2><<<gf, 256, SMEM_TOT>>>(xh, xl, tTh[0], tTl[0],
                                      nullptr, nullptr, nullptr, nullptr, bias, out, 0.f, 0.f);
}

// round 6
// speedup vs baseline: 7.3062x; 1.1488x over previous
#include <cuda_runtime.h>
#include <cuda_bf16.h>
#include <math.h>
#include <stdint.h>

// Problem dims (fixed by the dataset)
#define D      2048
#define TOKENS 8192

#define POW_ITERS 8
#define NQ 8        // quintic Newton-Schulz iterations
#define NC 4        // cubic polish iterations (NQ+NC even -> result in set 0)

// GEMM tiling: CTA 128x128, 8 warps (2 x 4), warp tile 64x32, K-chunk 64
#define KC 64
#define KSTAGES (D / KC)         // 32
#define RS 72                    // smem row stride in bf16 (144B: 4-bank row skew, ldmatrix conflict-free)
#define MAT_BYTES (128 * RS * 2) // 18432
#define STG_BYTES (4 * MAT_BYTES) // Ah | Al | Bh | Bl = 73728
#define NSTAGE 3
#define SMEM_TOT (NSTAGE * STG_BYTES)  // 221184

#define NTILE 16                 // D/128
#define NTRI  (NTILE * (NTILE + 1) / 2)   // 136 upper-triangular tiles

typedef __nv_bfloat16 bf16;

// ---------------- scratch (no allocs allowed) ----------------
__device__ __align__(16) bf16 g_th [2][(size_t)D * D];
__device__ __align__(16) bf16 g_tl [2][(size_t)D * D];
__device__ __align__(16) bf16 g_tTh[2][(size_t)D * D];
__device__ __align__(16) bf16 g_tTl[2][(size_t)D * D];
__device__ __align__(16) bf16 g_Gh[(size_t)D * D];
__device__ __align__(16) bf16 g_Gl[(size_t)D * D];
__device__ __align__(16) bf16 g_Hh[(size_t)D * D];
__device__ __align__(16) bf16 g_Hl[(size_t)D * D];
__device__ __align__(16) bf16 g_Wb[(size_t)D * D];
__device__ __align__(16) bf16 g_xh[(size_t)TOKENS * D];
__device__ __align__(16) bf16 g_xl[(size_t)TOKENS * D];
__device__ __align__(16) float g_u[D];
__device__ __align__(16) float g_v[D];
__device__ __align__(16) float g_part[32 * D];
__device__ float g_sigma;

// ---------------- PTX helpers (base ISA only: sm_80+) ----------------
static __device__ __forceinline__ uint32_t s2u(const void* p) {
    uint32_t a;
    asm("{ .reg .u64 t; cvta.to.shared.u64 t, %1; cvt.u32.u64 %0, t; }" : "=r"(a) : "l"(p));
    return a;
}
static __device__ __forceinline__ void cp16(uint32_t dst, const void* src) {
    asm volatile("cp.async.cg.shared.global [%0], [%1], 16;" :: "r"(dst), "l"(src));
}
static __device__ __forceinline__ void cp_commit() {
    asm volatile("cp.async.commit_group;" ::: "memory");
}
template<int N> static __device__ __forceinline__ void cp_wait() {
    asm volatile("cp.async.wait_group %0;" :: "n"(N) : "memory");
}
#define LDSM_X4(r, addr) \
    asm volatile("ldmatrix.sync.aligned.m8n8.x4.shared.b16 {%0,%1,%2,%3}, [%4];" \
        : "=r"((r)[0]), "=r"((r)[1]), "=r"((r)[2]), "=r"((r)[3]) : "r"(addr))
#define MMA16816(d, a, b) \
    asm volatile("mma.sync.aligned.m16n8k16.row.col.f32.bf16.bf16.f32 " \
        "{%0,%1,%2,%3}, {%4,%5,%6,%7}, {%8,%9}, {%0,%1,%2,%3};" \
        : "+f"((d)[0]), "+f"((d)[1]), "+f"((d)[2]), "+f"((d)[3]) \
        : "r"((a)[0]), "r"((a)[1]), "r"((a)[2]), "r"((a)[3]), "r"((b)[0]), "r"((b)[1]))

static __device__ __forceinline__ void split2(float v, bf16& h, bf16& l) {
    h = __float2bfloat16(v);
    l = __float2bfloat16(v - __bfloat162float(h));
}

// ---------------- power iteration kernels (bf16 W copy for bandwidth) ----------------
__global__ void w2bf_k(const float* __restrict__ W, bf16* __restrict__ Wb) {
    size_t i = (size_t)blockIdx.x * 256 + threadIdx.x;
    Wb[i] = __float2bfloat16(W[i]);
}

__global__ void colmean_k(const float* __restrict__ W, float* __restrict__ u) {
    int j = blockIdx.x * blockDim.x + threadIdx.x;
    float s = 0.f;
    for (int i = 0; i < D; ++i) s += W[(size_t)i * D + j];
    u[j] = s * (1.0f / D);
}

__global__ void normalize_k(float* __restrict__ v, float* __restrict__ out_norm) {
    __shared__ float red[1024];
    int t = threadIdx.x;
    float s = 0.f;
    for (int i = t; i < D; i += 1024) { float x = v[i]; s += x * x; }
    red[t] = s;
    __syncthreads();
    for (int o = 512; o > 0; o >>= 1) {
        if (t < o) red[t] += red[t + o];
        __syncthreads();
    }
    if (t == 0) {
        float nrm = sqrtf(red[0]);
        if (out_norm) *out_norm = nrm;
        red[0] = 1.0f / (nrm + 1e-10f);
    }
    __syncthreads();
    float iv = red[0];
    for (int i = t; i < D; i += 1024) v[i] *= iv;
}

// y = Wb @ u   (one warp per row; bf16 row, fp32 accumulate)
__global__ void bmatvec_row_k(const bf16* __restrict__ Wb, const float* __restrict__ u,
                              float* __restrict__ y) {
    int warp = threadIdx.x >> 5, lane = threadIdx.x & 31;
    int row = blockIdx.x * 8 + warp;
    const __nv_bfloat162* wr = (const __nv_bfloat162*)(Wb + (size_t)row * D);
    float s = 0.f;
    #pragma unroll 4
    for (int c = lane; c < D / 2; c += 32) {
        float2 w = __bfloat1622float2(wr[c]);
        s += w.x * u[2 * c] + w.y * u[2 * c + 1];
    }
    #pragma unroll
    for (int o = 16; o > 0; o >>= 1) s += __shfl_xor_sync(0xffffffffu, s, o);
    if (lane == 0) y[row] = s;
}

// part[by][j] = sum over 64-row chunk of v[i] * Wb[i][j]
__global__ void bmatvec_col_part_k(const bf16* __restrict__ Wb, const float* __restrict__ v,
                                   float* __restrict__ part) {
    int j = blockIdx.x * 256 + threadIdx.x;
    int r0 = blockIdx.y * 64;
    float s = 0.f;
    #pragma unroll 8
    for (int i = 0; i < 64; ++i)
        s += v[r0 + i] * __bfloat162float(Wb[(size_t)(r0 + i) * D + j]);
    part[blockIdx.y * D + j] = s;
}

__global__ void part_reduce_k(const float* __restrict__ part, float* __restrict__ z) {
    int j = blockIdx.x * 256 + threadIdx.x;
    float s = 0.f;
    #pragma unroll
    for (int c = 0; c < 32; ++c) s += part[c * D + j];
    z[j] = s;
}

// ---------------- prep: theta0 = W/sigma, split hi/lo, both orientations ----------------
__global__ void prep_theta_k(const float* __restrict__ W, const float* __restrict__ sig,
                             bf16* __restrict__ th, bf16* __restrict__ tl,
                             bf16* __restrict__ tTh, bf16* __restrict__ tTl) {
    __shared__ float s[32][33];
    float inv = 1.0f / (*sig + 1e-5f);
    int r = blockIdx.y * 32 + threadIdx.y;
    int c = blockIdx.x * 32 + threadIdx.x;
    float v = W[(size_t)r * D + c] * inv;
    bf16 h, l;
    split2(v, h, l);
    th[(size_t)r * D + c] = h;
    tl[(size_t)r * D + c] = l;
    s[threadIdx.y][threadIdx.x] = v;
    __syncthreads();
    float v2 = s[threadIdx.x][threadIdx.y];
    int r2 = blockIdx.x * 32 + threadIdx.y;
    int c2 = blockIdx.y * 32 + threadIdx.x;
    split2(v2, h, l);
    tTh[(size_t)r2 * D + c2] = h;
    tTl[(size_t)r2 * D + c2] = l;
}

__global__ void split_x_k(const float* __restrict__ x,
                          bf16* __restrict__ xh, bf16* __restrict__ xl) {
    size_t i = (size_t)blockIdx.x * 256 + threadIdx.x;
    bf16 h, l;
    split2(x[i], h, l);
    xh[i] = h; xl[i] = l;
}

// ---------------- split-bf16 mma.sync GEMM ----------------
// C[m][n] = sum_k A[m][k]*B[n][k] with A ~ Ah+Al, B ~ Bh+Bl (hh + hl + lh).
// EPI 0: G-sym  : triangular 1D grid; store split(acc) at BOTH (r,c) and (c,r) in Oh/Ol
// EPI 3: H-sym  : triangular 1D grid; v = alpha*A[m][n] + beta*acc; store both orientations in Oh/Ol
// EPI 1: update : full grid; v = alpha*A[m][n] + beta*acc; store normal Oh/Ol + transposed OTh/OTl
// EPI 2: out    : full grid; Of = acc + bias[n]
static __device__ __forceinline__ void load_stage(
    uint32_t sb, int buf, int kc, int tid, int row0, int col0,
    const bf16* __restrict__ Ah, const bf16* __restrict__ Al,
    const bf16* __restrict__ Bh, const bf16* __restrict__ Bl) {
    uint32_t base = sb + buf * STG_BYTES;
    const bf16* mats[4] = { Ah, Al, Bh, Bl };
    #pragma unroll
    for (int mat = 0; mat < 4; ++mat) {
        int base_row = (mat < 2) ? row0 : col0;
        uint32_t mb = base + mat * MAT_BYTES;
        const bf16* src0 = mats[mat] + (size_t)base_row * D + kc;
        #pragma unroll
        for (int it = 0; it < 4; ++it) {
            int idx = tid + it * 256;       // 1024 chunks: 128 rows x 8 x 16B
            int r = idx >> 3, c = idx & 7;
            cp16(mb + r * (RS * 2) + c * 16, src0 + (size_t)r * D + c * 8);
        }
    }
}

template<int EPI>
__global__ void __launch_bounds__(256, 1) mgemm_k(
    const bf16* __restrict__ Ah, const bf16* __restrict__ Al,
    const bf16* __restrict__ Bh, const bf16* __restrict__ Bl,
    bf16* __restrict__ Oh, bf16* __restrict__ Ol,
    bf16* __restrict__ OTh, bf16* __restrict__ OTl,
    const float* __restrict__ bias, float* __restrict__ Of,
    float alpha, float beta) {
    extern __shared__ char smem[];
    const uint32_t sb = s2u(smem);
    const int tid = threadIdx.x, wid = tid >> 5, lane = tid & 31;
    const int warp_m = wid & 1, warp_n = wid >> 1;

    int row0, col0;
    if (EPI == 0 || EPI == 3) {
        // map linear block -> upper-triangular tile (bi <= bj)
        int b = blockIdx.x, bi = 0;
        #pragma unroll 1
        while (b >= (NTILE - bi)) { b -= (NTILE - bi); ++bi; }
        row0 = bi * 128;
        col0 = (bi + b) * 128;
    } else {
        row0 = blockIdx.y * 128;
        col0 = blockIdx.x * 128;
    }

    // per-lane ldmatrix byte offsets within a tile
    uint32_t aoff[4], boff[2];
    #pragma unroll
    for (int mf = 0; mf < 4; ++mf)
        aoff[mf] = (uint32_t)((warp_m * 64 + mf * 16 + (lane & 15)) * (RS * 2) + (lane >> 4) * 16);
    #pragma unroll
    for (int n2 = 0; n2 < 2; ++n2)
        boff[n2] = (uint32_t)((warp_n * 32 + n2 * 16 + (lane & 7) + ((lane >> 4) & 1) * 8) * (RS * 2)
                              + ((lane >> 3) & 1) * 16);

    float acc[4][4][4];
    #pragma unroll
    for (int mf = 0; mf < 4; ++mf)
        #pragma unroll
        for (int nf = 0; nf < 4; ++nf)
            #pragma unroll
            for (int i = 0; i < 4; ++i) acc[mf][nf][i] = 0.f;

    // prefetch 2 stages
    #pragma unroll
    for (int s = 0; s < 2; ++s) {
        load_stage(sb, s, s * KC, tid, row0, col0, Ah, Al, Bh, Bl);
        cp_commit();
    }

    int buf = 0;
    for (int s = 0; s < KSTAGES; ++s) {
        cp_wait<1>();
        __syncthreads();
        if (s + 2 < KSTAGES) {
            int nb = buf + 2; if (nb >= 3) nb -= 3;
            load_stage(sb, nb, (s + 2) * KC, tid, row0, col0, Ah, Al, Bh, Bl);
        }
        cp_commit();

        uint32_t abase = sb + buf * STG_BYTES;
        uint32_t bbase = abase + 2 * MAT_BYTES;
        #pragma unroll
        for (int s2 = 0; s2 < 4; ++s2) {
            uint32_t ah[4][4], al[4][4], bh[8], bl[8];
            uint32_t ko = s2 * 32;
            #pragma unroll
            for (int mf = 0; mf < 4; ++mf) LDSM_X4(ah[mf], abase + aoff[mf] + ko);
            #pragma unroll
            for (int mf = 0; mf < 4; ++mf) LDSM_X4(al[mf], abase + MAT_BYTES + aoff[mf] + ko);
            #pragma unroll
            for (int n2 = 0; n2 < 2; ++n2) LDSM_X4(&bh[n2 * 4], bbase + boff[n2] + ko);
            #pragma unroll
            for (int n2 = 0; n2 < 2; ++n2) LDSM_X4(&bl[n2 * 4], bbase + MAT_BYTES + boff[n2] + ko);
            #pragma unroll
            for (int mf = 0; mf < 4; ++mf)
                #pragma unroll
                for (int nf = 0; nf < 4; ++nf) {
                    MMA16816(acc[mf][nf], ah[mf], &bh[nf * 2]);
                    MMA16816(acc[mf][nf], ah[mf], &bl[nf * 2]);
                    MMA16816(acc[mf][nf], al[mf], &bh[nf * 2]);
                }
        }
        if (++buf == 3) buf = 0;
    }
    __syncthreads();   // pipeline done; smem reused as epilogue staging

    // ---- stage acc into smem: per warp a 64x33 fp32 tile ----
    float* stg = (float*)smem + wid * (64 * 33);
    #pragma unroll
    for (int mf = 0; mf < 4; ++mf)
        #pragma unroll
        for (int nf = 0; nf < 4; ++nf) {
            int r = mf * 16 + (lane >> 2);
            int c = nf * 8 + 2 * (lane & 3);
            stg[r * 33 + c]           = acc[mf][nf][0];
            stg[r * 33 + c + 1]       = acc[mf][nf][1];
            stg[(r + 8) * 33 + c]     = acc[mf][nf][2];
            stg[(r + 8) * 33 + c + 1] = acc[mf][nf][3];
        }
    __syncwarp();

    const int rb = row0 + warp_m * 64;
    const int cb = col0 + warp_n * 32;

    if (EPI == 0) {
        // normal orientation
        #pragma unroll 4
        for (int r = 0; r < 64; ++r) {
            float v = stg[r * 33 + lane];
            bf16 hh, ll; split2(v, hh, ll);
            size_t a = (size_t)(rb + r) * D + cb + lane;
            Oh[a] = hh; Ol[a] = ll;
        }
        // mirrored orientation (symmetric output)
        #pragma unroll 4
        for (int c = 0; c < 32; ++c)
            #pragma unroll
            for (int h = 0; h < 2; ++h) {
                float v = stg[(lane + 32 * h) * 33 + c];
                bf16 hh, ll; split2(v, hh, ll);
                size_t a = (size_t)(cb + c) * D + rb + lane + 32 * h;
                Oh[a] = hh; Ol[a] = ll;
            }
    } else if (EPI == 2) {
        float bv = bias[cb + lane];
        #pragma unroll 4
        for (int r = 0; r < 64; ++r)
            Of[(size_t)(rb + r) * D + cb + lane] = stg[r * 33 + lane] + bv;
    } else {   // EPI 1 / 3: affine v = alpha*A + beta*acc, write normal + mirrored
        #pragma unroll 4
        for (int r = 0; r < 64; ++r) {
            size_t a = (size_t)(rb + r) * D + cb + lane;
            float tv = __bfloat162float(Ah[a]) + __bfloat162float(Al[a]);
            float v = alpha * tv + beta * stg[r * 33 + lane];
            stg[r * 33 + lane] = v;
            bf16 hh, ll; split2(v, hh, ll);
            Oh[a] = hh; Ol[a] = ll;
        }
        __syncwarp();
        bf16* Th = (EPI == 1) ? OTh : Oh;
        bf16* Tl = (EPI == 1) ? OTl : Ol;
        #pragma unroll 4
        for (int c = 0; c < 32; ++c)
            #pragma unroll
            for (int h = 0; h < 2; ++h) {
                float v = stg[(lane + 32 * h) * 33 + c];
                bf16 hh, ll; split2(v, hh, ll);
                size_t a = (size_t)(cb + c) * D + rb + lane + 32 * h;
                Th[a] = hh; Tl[a] = ll;
            }
    }
}

// ---------------- host orchestration ----------------
extern "C" void kernel_launch(void* const* d_in, const int* in_sizes, int n_in,
                              void* d_out, int out_size) {
    const float* x    = (const float*)d_in[0];   // [TOKENS, D]
    const float* W    = (const float*)d_in[1];   // [D, D]
    const float* bias = (const float*)d_in[2];   // [D]
    float* out = (float*)d_out;                  // [TOKENS, D]

    cudaFuncSetAttribute(mgemm_k<0>, cudaFuncAttributeMaxDynamicSharedMemorySize, SMEM_TOT);
    cudaFuncSetAttribute(mgemm_k<1>, cudaFuncAttributeMaxDynamicSharedMemorySize, SMEM_TOT);
    cudaFuncSetAttribute(mgemm_k<2>, cudaFuncAttributeMaxDynamicSharedMemorySize, SMEM_TOT);
    cudaFuncSetAttribute(mgemm_k<3>, cudaFuncAttributeMaxDynamicSharedMemorySize, SMEM_TOT);

    bf16 *thB, *tlB, *tThB, *tTlB, *Gh, *Gl, *Hh, *Hl, *Wb, *xh, *xl;
    float *u, *v, *part, *sig;
    cudaGetSymbolAddress((void**)&thB,  g_th);
    cudaGetSymbolAddress((void**)&tlB,  g_tl);
    cudaGetSymbolAddress((void**)&tThB, g_tTh);
    cudaGetSymbolAddress((void**)&tTlB, g_tTl);
    cudaGetSymbolAddress((void**)&Gh,   g_Gh);
    cudaGetSymbolAddress((void**)&Gl,   g_Gl);
    cudaGetSymbolAddress((void**)&Hh,   g_Hh);
    cudaGetSymbolAddress((void**)&Hl,   g_Hl);
    cudaGetSymbolAddress((void**)&Wb,   g_Wb);
    cudaGetSymbolAddress((void**)&xh,   g_xh);
    cudaGetSymbolAddress((void**)&xl,   g_xl);
    cudaGetSymbolAddress((void**)&u,    g_u);
    cudaGetSymbolAddress((void**)&v,    g_v);
    cudaGetSymbolAddress((void**)&part, g_part);
    cudaGetSymbolAddress((void**)&sig,  g_sigma);

    const size_t DD = (size_t)D * D;
    bf16* th[2]  = { thB,  thB  + DD };
    bf16* tl[2]  = { tlB,  tlB  + DD };
    bf16* tTh[2] = { tThB, tThB + DD };
    bf16* tTl[2] = { tTlB, tTlB + DD };

    // ---- power iteration on a bf16 copy of W (half the traffic). Direction is
    // scale-invariant, so intermediate normalizes are skipped (norms grow ~4x/iter;
    // 4^8 ~ 65536, safe in fp32). sigma estimate only needs a few % accuracy. ----
    w2bf_k<<<(unsigned)(DD / 256), 256>>>(W, Wb);
    colmean_k<<<D / 256, 256>>>(W, u);
    normalize_k<<<1, 1024>>>(u, nullptr);
    for (int it = 0; it < POW_ITERS; ++it) {
        bmatvec_row_k<<<D / 8, 256>>>(Wb, u, v);
        bmatvec_col_part_k<<<dim3(D / 256, 32), 256>>>(Wb, v, part);
        part_reduce_k<<<D / 256, 256>>>(part, u);
    }
    normalize_k<<<1, 1024>>>(u, nullptr);
    bmatvec_row_k<<<D / 8, 256>>>(Wb, u, v);
    normalize_k<<<1, 1024>>>(v, sig);         // sigma = ||W u|| (bf16-accurate, ~0.4%)

    // ---- theta0 = W/sigma split bf16 both orientations; split x ----
    prep_theta_k<<<dim3(64, 64), dim3(32, 32)>>>(W, sig, th[0], tl[0], tTh[0], tTl[0]);
    split_x_k<<<(unsigned)((size_t)TOKENS * D / 256), 256>>>(x, xh, xl);

    const float a5 = 3.4445f, b5 = -4.7750f, c5 = 2.0315f;
    dim3 gsq(NTILE, NTILE);                   // full 16 x 16
    dim3 gtri(NTRI);                          // 136 triangular tiles (one wave)

    // ---- quintic Newton-Schulz: theta <- a*theta + theta*(b*G + c*G^2) ----
    for (int it = 0; it < NQ; ++it) {
        int p = it & 1, q = p ^ 1;
        mgemm_k<0><<<gtri, 256, SMEM_TOT>>>(tTh[p], tTl[p], tTh[p], tTl[p],
                                            Gh, Gl, nullptr, nullptr, nullptr, nullptr, 0.f, 0.f);
        mgemm_k<3><<<gtri, 256, SMEM_TOT>>>(Gh, Gl, Gh, Gl,
                                            Hh, Hl, nullptr, nullptr, nullptr, nullptr, b5, c5);
        mgemm_k<1><<<gsq, 256, SMEM_TOT>>>(th[p], tl[p], Hh, Hl,
                                           th[q], tl[q], tTh[q], tTl[q], nullptr, nullptr, a5, 1.0f);
    }
    // ---- cubic polish: theta <- 1.5*theta - 0.5*theta*G ----
    for (int it = NQ; it < NQ + NC; ++it) {
        int p = it & 1, q = p ^ 1;
        mgemm_k<0><<<gtri, 256, SMEM_TOT>>>(tTh[p], tTl[p], tTh[p], tTl[p],
                                            Gh, Gl, nullptr, nullptr, nullptr, nullptr, 0.f, 0.f);
        mgemm_k<1><<<gsq, 256, SMEM_TOT>>>(th[p], tl[p], Gh, Gl,
                                           th[q], tl[q], tTh[q], tTl[q], nullptr, nullptr, 1.5f, -0.5f);
    }
    // (NQ + NC) even -> final theta in set 0

    // ---- out = x @ theta + bias ----
    dim3 gf(NTILE, TOKENS / 128);             // 16 x 64
    mgemm_k<2><<<gf, 256, SMEM_TOT>>>(xh, xl, tTh[0], tTl[0],
                                      nullptr, nullptr, nullptr, nullptr, bias, out, 0.f, 0.f);
}

// round 7
// speedup vs baseline: 7.3318x; 1.0035x over previous
#include <cuda_runtime.h>
#include <cuda_bf16.h>
#include <math.h>
#include <stdint.h>

// Problem dims (fixed by the dataset)
#define D      2048
#define TOKENS 8192

#define POW_ITERS 8
#define NQ 8        // quintic Newton-Schulz iterations
#define NC 4        // cubic polish iterations (NQ+NC even -> result in set 0)

// GEMM tiling: CTA 128x128, 8 warps (2 x 4), warp tile 64x32, K-chunk 64
#define KC 64
#define KSTAGES (D / KC)         // 32
#define RS 72                    // smem row stride in bf16 (144B: 4-bank row skew, ldmatrix conflict-free)
#define MAT_BYTES (128 * RS * 2) // 18432
#define STG_BYTES (4 * MAT_BYTES) // Ah | Al | Bh | Bl = 73728
#define NSTAGE 3
#define SMEM_TOT (NSTAGE * STG_BYTES)  // 221184

#define NTILE 16                 // D/128
#define NTRI  (NTILE * (NTILE + 1) / 2)   // 136 upper-triangular tiles

typedef __nv_bfloat16 bf16;

// ---------------- scratch (no allocs allowed) ----------------
__device__ __align__(16) bf16 g_th [2][(size_t)D * D];
__device__ __align__(16) bf16 g_tl [2][(size_t)D * D];
__device__ __align__(16) bf16 g_tTh[2][(size_t)D * D];
__device__ __align__(16) bf16 g_tTl[2][(size_t)D * D];
__device__ __align__(16) bf16 g_Gh[(size_t)D * D];
__device__ __align__(16) bf16 g_Gl[(size_t)D * D];
__device__ __align__(16) bf16 g_Hh[(size_t)D * D];
__device__ __align__(16) bf16 g_Hl[(size_t)D * D];
__device__ __align__(16) bf16 g_Wb[(size_t)D * D];
__device__ __align__(16) bf16 g_xh[(size_t)TOKENS * D];
__device__ __align__(16) bf16 g_xl[(size_t)TOKENS * D];
__device__ __align__(16) float g_u[D];
__device__ __align__(16) float g_v[D];
__device__ __align__(16) float g_part[32 * D];
__device__ float g_sigma;

// ---------------- PTX helpers (base ISA only: sm_80+) ----------------
static __device__ __forceinline__ uint32_t s2u(const void* p) {
    uint32_t a;
    asm("{ .reg .u64 t; cvta.to.shared.u64 t, %1; cvt.u32.u64 %0, t; }" : "=r"(a) : "l"(p));
    return a;
}
static __device__ __forceinline__ void cp16(uint32_t dst, const void* src) {
    asm volatile("cp.async.cg.shared.global [%0], [%1], 16;" :: "r"(dst), "l"(src));
}
static __device__ __forceinline__ void cp_commit() {
    asm volatile("cp.async.commit_group;" ::: "memory");
}
template<int N> static __device__ __forceinline__ void cp_wait() {
    asm volatile("cp.async.wait_group %0;" :: "n"(N) : "memory");
}
#define LDSM_X4(r, addr) \
    asm volatile("ldmatrix.sync.aligned.m8n8.x4.shared.b16 {%0,%1,%2,%3}, [%4];" \
        : "=r"((r)[0]), "=r"((r)[1]), "=r"((r)[2]), "=r"((r)[3]) : "r"(addr))
#define MMA16816(d, a, b) \
    asm volatile("mma.sync.aligned.m16n8k16.row.col.f32.bf16.bf16.f32 " \
        "{%0,%1,%2,%3}, {%4,%5,%6,%7}, {%8,%9}, {%0,%1,%2,%3};" \
        : "+f"((d)[0]), "+f"((d)[1]), "+f"((d)[2]), "+f"((d)[3]) \
        : "r"((a)[0]), "r"((a)[1]), "r"((a)[2]), "r"((a)[3]), "r"((b)[0]), "r"((b)[1]))

static __device__ __forceinline__ void split2(float v, bf16& h, bf16& l) {
    h = __float2bfloat16(v);
    l = __float2bfloat16(v - __bfloat162float(h));
}

// ---------------- power iteration kernels (bf16 W copy for bandwidth) ----------------
__global__ void w2bf_k(const float* __restrict__ W, bf16* __restrict__ Wb) {
    size_t i = (size_t)blockIdx.x * 256 + threadIdx.x;
    Wb[i] = __float2bfloat16(W[i]);
}

__global__ void colmean_k(const float* __restrict__ W, float* __restrict__ u) {
    int j = blockIdx.x * blockDim.x + threadIdx.x;
    float s = 0.f;
    for (int i = 0; i < D; ++i) s += W[(size_t)i * D + j];
    u[j] = s * (1.0f / D);
}

__global__ void normalize_k(float* __restrict__ v, float* __restrict__ out_norm) {
    __shared__ float red[1024];
    int t = threadIdx.x;
    float s = 0.f;
    for (int i = t; i < D; i += 1024) { float x = v[i]; s += x * x; }
    red[t] = s;
    __syncthreads();
    for (int o = 512; o > 0; o >>= 1) {
        if (t < o) red[t] += red[t + o];
        __syncthreads();
    }
    if (t == 0) {
        float nrm = sqrtf(red[0]);
        if (out_norm) *out_norm = nrm;
        red[0] = 1.0f / (nrm + 1e-10f);
    }
    __syncthreads();
    float iv = red[0];
    for (int i = t; i < D; i += 1024) v[i] *= iv;
}

// y = Wb @ u   (one warp per row; bf16 row, fp32 accumulate)
__global__ void bmatvec_row_k(const bf16* __restrict__ Wb, const float* __restrict__ u,
                              float* __restrict__ y) {
    int warp = threadIdx.x >> 5, lane = threadIdx.x & 31;
    int row = blockIdx.x * 8 + warp;
    const __nv_bfloat162* wr = (const __nv_bfloat162*)(Wb + (size_t)row * D);
    float s = 0.f;
    #pragma unroll 4
    for (int c = lane; c < D / 2; c += 32) {
        float2 w = __bfloat1622float2(wr[c]);
        s += w.x * u[2 * c] + w.y * u[2 * c + 1];
    }
    #pragma unroll
    for (int o = 16; o > 0; o >>= 1) s += __shfl_xor_sync(0xffffffffu, s, o);
    if (lane == 0) y[row] = s;
}

// part[by][j] = sum over 64-row chunk of v[i] * Wb[i][j]
__global__ void bmatvec_col_part_k(const bf16* __restrict__ Wb, const float* __restrict__ v,
                                   float* __restrict__ part) {
    int j = blockIdx.x * 256 + threadIdx.x;
    int r0 = blockIdx.y * 64;
    float s = 0.f;
    #pragma unroll 8
    for (int i = 0; i < 64; ++i)
        s += v[r0 + i] * __bfloat162float(Wb[(size_t)(r0 + i) * D + j]);
    part[blockIdx.y * D + j] = s;
}

__global__ void part_reduce_k(const float* __restrict__ part, float* __restrict__ z) {
    int j = blockIdx.x * 256 + threadIdx.x;
    float s = 0.f;
    #pragma unroll
    for (int c = 0; c < 32; ++c) s += part[c * D + j];
    z[j] = s;
}

// ---------------- prep: theta0 = W/sigma, split hi/lo, both orientations ----------------
__global__ void prep_theta_k(const float* __restrict__ W, const float* __restrict__ sig,
                             bf16* __restrict__ th, bf16* __restrict__ tl,
                             bf16* __restrict__ tTh, bf16* __restrict__ tTl) {
    __shared__ float s[32][33];
    float inv = 1.0f / (*sig + 1e-5f);
    int r = blockIdx.y * 32 + threadIdx.y;
    int c = blockIdx.x * 32 + threadIdx.x;
    float v = W[(size_t)r * D + c] * inv;
    bf16 h, l;
    split2(v, h, l);
    th[(size_t)r * D + c] = h;
    tl[(size_t)r * D + c] = l;
    s[threadIdx.y][threadIdx.x] = v;
    __syncthreads();
    float v2 = s[threadIdx.x][threadIdx.y];
    int r2 = blockIdx.x * 32 + threadIdx.y;
    int c2 = blockIdx.y * 32 + threadIdx.x;
    split2(v2, h, l);
    tTh[(size_t)r2 * D + c2] = h;
    tTl[(size_t)r2 * D + c2] = l;
}

__global__ void split_x_k(const float* __restrict__ x,
                          bf16* __restrict__ xh, bf16* __restrict__ xl) {
    size_t i = (size_t)blockIdx.x * 256 + threadIdx.x;
    bf16 h, l;
    split2(x[i], h, l);
    xh[i] = h; xl[i] = l;
}

// ---------------- split-bf16 mma.sync GEMM ----------------
// C[m][n] = sum_k A[m][k]*B[n][k] with A ~ Ah+Al, B ~ Bh+Bl (hh + hl + lh).
// EPI 0: G-sym  : triangular 1D grid; store split(acc) at BOTH (r,c) and (c,r) in Oh/Ol
// EPI 3: H-sym  : triangular 1D grid; v = alpha*A[m][n] + beta*acc; store both orientations in Oh/Ol
// EPI 1: update : full grid; v = alpha*A[m][n] + beta*acc; store normal Oh/Ol + transposed OTh/OTl
// EPI 2: out    : full grid; Of = acc + bias[n]
static __device__ __forceinline__ void load_stage(
    uint32_t sb, int buf, int kc, int tid, int row0, int col0,
    const bf16* __restrict__ Ah, const bf16* __restrict__ Al,
    const bf16* __restrict__ Bh, const bf16* __restrict__ Bl) {
    uint32_t base = sb + buf * STG_BYTES;
    const bf16* mats[4] = { Ah, Al, Bh, Bl };
    #pragma unroll
    for (int mat = 0; mat < 4; ++mat) {
        int base_row = (mat < 2) ? row0 : col0;
        uint32_t mb = base + mat * MAT_BYTES;
        const bf16* src0 = mats[mat] + (size_t)base_row * D + kc;
        #pragma unroll
        for (int it = 0; it < 4; ++it) {
            int idx = tid + it * 256;       // 1024 chunks: 128 rows x 8 x 16B
            int r = idx >> 3, c = idx & 7;
            cp16(mb + r * (RS * 2) + c * 16, src0 + (size_t)r * D + c * 8);
        }
    }
}

template<int EPI>
__global__ void __launch_bounds__(256, 1) mgemm_k(
    const bf16* __restrict__ Ah, const bf16* __restrict__ Al,
    const bf16* __restrict__ Bh, const bf16* __restrict__ Bl,
    bf16* __restrict__ Oh, bf16* __restrict__ Ol,
    bf16* __restrict__ OTh, bf16* __restrict__ OTl,
    const float* __restrict__ bias, float* __restrict__ Of,
    float alpha, float beta) {
    extern __shared__ char smem[];
    const uint32_t sb = s2u(smem);
    const int tid = threadIdx.x, wid = tid >> 5, lane = tid & 31;
    const int warp_m = wid & 1, warp_n = wid >> 1;

    int row0, col0;
    if (EPI == 0 || EPI == 3) {
        // map linear block -> upper-triangular tile (bi <= bj)
        int b = blockIdx.x, bi = 0;
        #pragma unroll 1
        while (b >= (NTILE - bi)) { b -= (NTILE - bi); ++bi; }
        row0 = bi * 128;
        col0 = (bi + b) * 128;
    } else {
        row0 = blockIdx.y * 128;
        col0 = blockIdx.x * 128;
    }

    // per-lane ldmatrix byte offsets within a tile
    uint32_t aoff[4], boff[2];
    #pragma unroll
    for (int mf = 0; mf < 4; ++mf)
        aoff[mf] = (uint32_t)((warp_m * 64 + mf * 16 + (lane & 15)) * (RS * 2) + (lane >> 4) * 16);
    #pragma unroll
    for (int n2 = 0; n2 < 2; ++n2)
        boff[n2] = (uint32_t)((warp_n * 32 + n2 * 16 + (lane & 7) + ((lane >> 4) & 1) * 8) * (RS * 2)
                              + ((lane >> 3) & 1) * 16);

    float acc[4][4][4];
    #pragma unroll
    for (int mf = 0; mf < 4; ++mf)
        #pragma unroll
        for (int nf = 0; nf < 4; ++nf)
            #pragma unroll
            for (int i = 0; i < 4; ++i) acc[mf][nf][i] = 0.f;

    // double-buffered fragments (slice-level software pipeline)
    uint32_t ah[2][4][4], al[2][4][4], bh[2][8], bl[2][8];

    // prefetch 2 stages
    #pragma unroll
    for (int s = 0; s < 2; ++s) {
        load_stage(sb, s, s * KC, tid, row0, col0, Ah, Al, Bh, Bl);
        cp_commit();
    }

    int buf = 0;
    for (int s = 0; s < KSTAGES; ++s) {
        cp_wait<1>();
        __syncthreads();
        if (s + 2 < KSTAGES) {
            int nb = buf + 2; if (nb >= 3) nb -= 3;
            load_stage(sb, nb, (s + 2) * KC, tid, row0, col0, Ah, Al, Bh, Bl);
        }
        cp_commit();

        uint32_t abase = sb + buf * STG_BYTES;
        uint32_t bbase = abase + 2 * MAT_BYTES;

        // load fragments for slice 0
        #pragma unroll
        for (int mf = 0; mf < 4; ++mf) LDSM_X4(ah[0][mf], abase + aoff[mf]);
        #pragma unroll
        for (int mf = 0; mf < 4; ++mf) LDSM_X4(al[0][mf], abase + MAT_BYTES + aoff[mf]);
        #pragma unroll
        for (int n2 = 0; n2 < 2; ++n2) LDSM_X4(&bh[0][n2 * 4], bbase + boff[n2]);
        #pragma unroll
        for (int n2 = 0; n2 < 2; ++n2) LDSM_X4(&bl[0][n2 * 4], bbase + MAT_BYTES + boff[n2]);

        #pragma unroll
        for (int s2 = 0; s2 < 4; ++s2) {
            const int cur = s2 & 1, nxt = cur ^ 1;
            if (s2 < 3) {          // prefetch next slice's fragments while doing MMAs
                uint32_t ko = (uint32_t)(s2 + 1) * 32;
                #pragma unroll
                for (int mf = 0; mf < 4; ++mf) LDSM_X4(ah[nxt][mf], abase + aoff[mf] + ko);
                #pragma unroll
                for (int mf = 0; mf < 4; ++mf) LDSM_X4(al[nxt][mf], abase + MAT_BYTES + aoff[mf] + ko);
                #pragma unroll
                for (int n2 = 0; n2 < 2; ++n2) LDSM_X4(&bh[nxt][n2 * 4], bbase + boff[n2] + ko);
                #pragma unroll
                for (int n2 = 0; n2 < 2; ++n2) LDSM_X4(&bl[nxt][n2 * 4], bbase + MAT_BYTES + boff[n2] + ko);
            }
            #pragma unroll
            for (int mf = 0; mf < 4; ++mf)
                #pragma unroll
                for (int nf = 0; nf < 4; ++nf) {
                    MMA16816(acc[mf][nf], ah[cur][mf], &bh[cur][nf * 2]);
                    MMA16816(acc[mf][nf], ah[cur][mf], &bl[cur][nf * 2]);
                    MMA16816(acc[mf][nf], al[cur][mf], &bh[cur][nf * 2]);
                }
        }
        if (++buf == 3) buf = 0;
    }
    __syncthreads();   // pipeline done; smem reused as epilogue staging

    // ---- stage acc into smem: per warp a 64x33 fp32 tile ----
    float* stg = (float*)smem + wid * (64 * 33);
    #pragma unroll
    for (int mf = 0; mf < 4; ++mf)
        #pragma unroll
        for (int nf = 0; nf < 4; ++nf) {
            int r = mf * 16 + (lane >> 2);
            int c = nf * 8 + 2 * (lane & 3);
            stg[r * 33 + c]           = acc[mf][nf][0];
            stg[r * 33 + c + 1]       = acc[mf][nf][1];
            stg[(r + 8) * 33 + c]     = acc[mf][nf][2];
            stg[(r + 8) * 33 + c + 1] = acc[mf][nf][3];
        }
    __syncwarp();

    const int rb = row0 + warp_m * 64;
    const int cb = col0 + warp_n * 32;

    if (EPI == 0) {
        // normal orientation
        #pragma unroll 4
        for (int r = 0; r < 64; ++r) {
            float v = stg[r * 33 + lane];
            bf16 hh, ll; split2(v, hh, ll);
            size_t a = (size_t)(rb + r) * D + cb + lane;
            Oh[a] = hh; Ol[a] = ll;
        }
        // mirrored orientation (symmetric output)
        #pragma unroll 4
        for (int c = 0; c < 32; ++c)
            #pragma unroll
            for (int h = 0; h < 2; ++h) {
                float v = stg[(lane + 32 * h) * 33 + c];
                bf16 hh, ll; split2(v, hh, ll);
                size_t a = (size_t)(cb + c) * D + rb + lane + 32 * h;
                Oh[a] = hh; Ol[a] = ll;
            }
    } else if (EPI == 2) {
        float bv = bias[cb + lane];
        #pragma unroll 4
        for (int r = 0; r < 64; ++r)
            Of[(size_t)(rb + r) * D + cb + lane] = stg[r * 33 + lane] + bv;
    } else {   // EPI 1 / 3: affine v = alpha*A + beta*acc, write normal + mirrored
        #pragma unroll 4
        for (int r = 0; r < 64; ++r) {
            size_t a = (size_t)(rb + r) * D + cb + lane;
            float tv = __bfloat162float(Ah[a]) + __bfloat162float(Al[a]);
            float v = alpha * tv + beta * stg[r * 33 + lane];
            stg[r * 33 + lane] = v;
            bf16 hh, ll; split2(v, hh, ll);
            Oh[a] = hh; Ol[a] = ll;
        }
        __syncwarp();
        bf16* Th = (EPI == 1) ? OTh : Oh;
        bf16* Tl = (EPI == 1) ? OTl : Ol;
        #pragma unroll 4
        for (int c = 0; c < 32; ++c)
            #pragma unroll
            for (int h = 0; h < 2; ++h) {
                float v = stg[(lane + 32 * h) * 33 + c];
                bf16 hh, ll; split2(v, hh, ll);
                size_t a = (size_t)(cb + c) * D + rb + lane + 32 * h;
                Th[a] = hh; Tl[a] = ll;
            }
    }
}

// ---------------- host orchestration ----------------
extern "C" void kernel_launch(void* const* d_in, const int* in_sizes, int n_in,
                              void* d_out, int out_size) {
    const float* x    = (const float*)d_in[0];   // [TOKENS, D]
    const float* W    = (const float*)d_in[1];   // [D, D]
    const float* bias = (const float*)d_in[2];   // [D]
    float* out = (float*)d_out;                  // [TOKENS, D]

    cudaFuncSetAttribute(mgemm_k<0>, cudaFuncAttributeMaxDynamicSharedMemorySize, SMEM_TOT);
    cudaFuncSetAttribute(mgemm_k<1>, cudaFuncAttributeMaxDynamicSharedMemorySize, SMEM_TOT);
    cudaFuncSetAttribute(mgemm_k<2>, cudaFuncAttributeMaxDynamicSharedMemorySize, SMEM_TOT);
    cudaFuncSetAttribute(mgemm_k<3>, cudaFuncAttributeMaxDynamicSharedMemorySize, SMEM_TOT);

    bf16 *thB, *tlB, *tThB, *tTlB, *Gh, *Gl, *Hh, *Hl, *Wb, *xh, *xl;
    float *u, *v, *part, *sig;
    cudaGetSymbolAddress((void**)&thB,  g_th);
    cudaGetSymbolAddress((void**)&tlB,  g_tl);
    cudaGetSymbolAddress((void**)&tThB, g_tTh);
    cudaGetSymbolAddress((void**)&tTlB, g_tTl);
    cudaGetSymbolAddress((void**)&Gh,   g_Gh);
    cudaGetSymbolAddress((void**)&Gl,   g_Gl);
    cudaGetSymbolAddress((void**)&Hh,   g_Hh);
    cudaGetSymbolAddress((void**)&Hl,   g_Hl);
    cudaGetSymbolAddress((void**)&Wb,   g_Wb);
    cudaGetSymbolAddress((void**)&xh,   g_xh);
    cudaGetSymbolAddress((void**)&xl,   g_xl);
    cudaGetSymbolAddress((void**)&u,    g_u);
    cudaGetSymbolAddress((void**)&v,    g_v);
    cudaGetSymbolAddress((void**)&part, g_part);
    cudaGetSymbolAddress((void**)&sig,  g_sigma);

    const size_t DD = (size_t)D * D;
    bf16* th[2]  = { thB,  thB  + DD };
    bf16* tl[2]  = { tlB,  tlB  + DD };
    bf16* tTh[2] = { tThB, tThB + DD };
    bf16* tTl[2] = { tTlB, tTlB + DD };

    // ---- power iteration on a bf16 copy of W (half the traffic). Direction is
    // scale-invariant, so intermediate normalizes are skipped (norms grow ~4x/iter;
    // 4^8 ~ 65536, safe in fp32). sigma estimate only needs a few % accuracy. ----
    w2bf_k<<<(unsigned)(DD / 256), 256>>>(W, Wb);
    colmean_k<<<D / 256, 256>>>(W, u);
    normalize_k<<<1, 1024>>>(u, nullptr);
    for (int it = 0; it < POW_ITERS; ++it) {
        bmatvec_row_k<<<D / 8, 256>>>(Wb, u, v);
        bmatvec_col_part_k<<<dim3(D / 256, 32), 256>>>(Wb, v, part);
        part_reduce_k<<<D / 256, 256>>>(part, u);
    }
    normalize_k<<<1, 1024>>>(u, nullptr);
    bmatvec_row_k<<<D / 8, 256>>>(Wb, u, v);
    normalize_k<<<1, 1024>>>(v, sig);         // sigma = ||W u|| (bf16-accurate, ~0.4%)

    // ---- theta0 = W/sigma split bf16 both orientations; split x ----
    prep_theta_k<<<dim3(64, 64), dim3(32, 32)>>>(W, sig, th[0], tl[0], tTh[0], tTl[0]);
    split_x_k<<<(unsigned)((size_t)TOKENS * D / 256), 256>>>(x, xh, xl);

    const float a5 = 3.4445f, b5 = -4.7750f, c5 = 2.0315f;
    dim3 gsq(NTILE, NTILE);                   // full 16 x 16
    dim3 gtri(NTRI);                          // 136 triangular tiles (one wave)

    // ---- quintic Newton-Schulz: theta <- a*theta + theta*(b*G + c*G^2) ----
    for (int it = 0; it < NQ; ++it) {
        int p = it & 1, q = p ^ 1;
        mgemm_k<0><<<gtri, 256, SMEM_TOT>>>(tTh[p], tTl[p], tTh[p], tTl[p],
                                            Gh, Gl, nullptr, nullptr, nullptr, nullptr, 0.f, 0.f);
        mgemm_k<3><<<gtri, 256, SMEM_TOT>>>(Gh, Gl, Gh, Gl,
                                            Hh, Hl, nullptr, nullptr, nullptr, nullptr, b5, c5);
        mgemm_k<1><<<gsq, 256, SMEM_TOT>>>(th[p], tl[p], Hh, Hl,
                                           th[q], tl[q], tTh[q], tTl[q], nullptr, nullptr, a5, 1.0f);
    }
    // ---- cubic polish: theta <- 1.5*theta - 0.5*theta*G ----
    for (int it = NQ; it < NQ + NC; ++it) {
        int p = it & 1, q = p ^ 1;
        mgemm_k<0><<<gtri, 256, SMEM_TOT>>>(tTh[p], tTl[p], tTh[p], tTl[p],
                                            Gh, Gl, nullptr, nullptr, nullptr, nullptr, 0.f, 0.f);
        mgemm_k<1><<<gsq, 256, SMEM_TOT>>>(th[p], tl[p], Gh, Gl,
                                           th[q], tl[q], tTh[q], tTl[q], nullptr, nullptr, 1.5f, -0.5f);
    }
    // (NQ + NC) even -> final theta in set 0

    // ---- out = x @ theta + bias ----
    dim3 gf(NTILE, TOKENS / 128);             // 16 x 64
    mgemm_k<2><<<gf, 256, SMEM_TOT>>>(xh, xl, tTh[0], tTl[0],
                                      nullptr, nullptr, nullptr, nullptr, bias, out, 0.f, 0.f);
}